// round 1
// baseline (speedup 1.0000x reference)
#include <cuda_runtime.h>
#include <math.h>

#define MAXN 100000
#define MAXE 600000
#define DD 128

// ---------------- static device scratch (no allocations allowed) ----------------
__device__ float g_Y[8L * MAXN * DD];      // 409.6 MB: Y_r = S_r X_r
__device__ float g_el[8 * MAXN];
__device__ float g_er[8 * MAXN];
__device__ float g_wal[8 * DD];
__device__ float g_war[8 * DD];
__device__ int   g_cnt[4 * MAXN];
__device__ int   g_rowptr[4 * MAXN];       // exclusive row offsets (global over 4 structs)
__device__ int   g_cursor[4 * MAXN];
__device__ int   g_col[4 * MAXE];
__device__ int   g_bsums[1024];
__device__ int   g_boffs[1024];

// ---------------- wal_r = W_r @ al_r, war_r = W_r @ ar_r ----------------
__global__ void k_prep(const float* __restrict__ W, const float* __restrict__ al,
                       const float* __restrict__ ar) {
    int r = blockIdx.x;          // 0..7
    int i = threadIdx.x;         // 0..127  (row of W)
    const float* Wr  = W + r * DD * DD + i * DD;
    const float* alr = al + r * DD;
    const float* arr = ar + r * DD;
    float sl = 0.f, sr = 0.f;
    #pragma unroll 8
    for (int j = 0; j < DD; j++) { float w = Wr[j]; sl += w * alr[j]; sr += w * arr[j]; }
    g_wal[r * DD + i] = sl;
    g_war[r * DD + i] = sr;
}

// ---------------- el[r][n], er[r][n] via 16 matvecs (warp per node) ----------------
__global__ void k_elr(const float* __restrict__ fsrc, const float* __restrict__ fdst, int n) {
    __shared__ float4 swal[8 * 32], swar[8 * 32];
    int tid = threadIdx.x;
    if (tid < 256) {
        swal[tid] = ((const float4*)g_wal)[tid];
        swar[tid] = ((const float4*)g_war)[tid];
    }
    __syncthreads();
    int warp = tid >> 5, lane = tid & 31;
    int node = blockIdx.x * 8 + warp;
    if (node >= n) return;
    float4 fs = ((const float4*)fsrc)[(long)node * 32 + lane];
    float4 fd = ((const float4*)fdst)[(long)node * 32 + lane];
    float p[16];
    #pragma unroll
    for (int r = 0; r < 8; r++) {
        float4 wl = swal[r * 32 + lane];
        float4 wr = swar[r * 32 + lane];
        bool useSrc = (r == 0 || r == 1 || r == 4 || r == 5);
        float4 x = useSrc ? fs : fd;
        p[r]     = x.x * wl.x + x.y * wl.y + x.z * wl.z + x.w * wl.w;
        p[8 + r] = fd.x * wr.x + fd.y * wr.y + fd.z * wr.z + fd.w * wr.w;
    }
    #pragma unroll
    for (int i = 0; i < 16; i++)
        #pragma unroll
        for (int o = 16; o; o >>= 1) p[i] += __shfl_xor_sync(0xffffffffu, p[i], o);
    if (lane == 0) {
        #pragma unroll
        for (int r = 0; r < 8; r++) {
            g_el[(long)r * n + node] = p[r];
            g_er[(long)r * n + node] = p[8 + r];
        }
    }
}

__global__ void k_zero(int len) {
    int i = blockIdx.x * blockDim.x + threadIdx.x;
    if (i < len) g_cnt[i] = 0;
}

// structures: 0 fwd-intra (key=intra_dst), 1 fwd-inter (key=inter_dst),
//             2 rev-intra (key=intra_src), 3 rev-inter (key=inter_src)
__global__ void k_hist(const int* __restrict__ isrc, const int* __restrict__ idst,
                       const int* __restrict__ xsrc, const int* __restrict__ xdst,
                       int n, int E) {
    int t = blockIdx.x * blockDim.x + threadIdx.x;
    if (t >= 4 * E) return;
    int s = t / E, e = t - s * E;
    int key = (s == 0) ? idst[e] : (s == 1) ? xdst[e] : (s == 2) ? isrc[e] : xsrc[e];
    atomicAdd(&g_cnt[s * n + key], 1);
}

__global__ void k_scan1(int len) {   // block-wise inclusive scan of g_cnt -> g_rowptr
    __shared__ int sm[1024];
    int i = blockIdx.x * 1024 + threadIdx.x;
    int v = (i < len) ? g_cnt[i] : 0;
    sm[threadIdx.x] = v;
    __syncthreads();
    for (int off = 1; off < 1024; off <<= 1) {
        int t = (threadIdx.x >= off) ? sm[threadIdx.x - off] : 0;
        __syncthreads();
        sm[threadIdx.x] += t;
        __syncthreads();
    }
    if (i < len) g_rowptr[i] = sm[threadIdx.x];
    if (threadIdx.x == 1023) g_bsums[blockIdx.x] = sm[1023];
}

__global__ void k_scan2(int nb) {    // exclusive scan of block sums (nb <= 512)
    __shared__ int sm[512];
    int v = (threadIdx.x < nb) ? g_bsums[threadIdx.x] : 0;
    sm[threadIdx.x] = v;
    __syncthreads();
    for (int off = 1; off < 512; off <<= 1) {
        int t = (threadIdx.x >= off) ? sm[threadIdx.x - off] : 0;
        __syncthreads();
        sm[threadIdx.x] += t;
        __syncthreads();
    }
    if (threadIdx.x < nb) g_boffs[threadIdx.x] = sm[threadIdx.x] - v;
}

__global__ void k_scan3(int len) {   // inclusive -> global exclusive; init cursor
    int i = blockIdx.x * 1024 + threadIdx.x;
    if (i >= len) return;
    int excl = g_rowptr[i] - g_cnt[i] + g_boffs[blockIdx.x];
    g_rowptr[i] = excl;
    g_cursor[i] = excl;
}

__global__ void k_fill(const int* __restrict__ isrc, const int* __restrict__ idst,
                       const int* __restrict__ xsrc, const int* __restrict__ xdst,
                       int n, int E) {
    int t = blockIdx.x * blockDim.x + threadIdx.x;
    if (t >= 4 * E) return;
    int s = t / E, e = t - s * E;
    int key, col;
    if (s == 0)      { key = idst[e]; col = isrc[e]; }
    else if (s == 1) { key = xdst[e]; col = xsrc[e]; }
    else if (s == 2) { key = isrc[e]; col = idst[e]; }
    else             { key = xsrc[e]; col = xdst[e]; }
    int pos = atomicAdd(&g_cursor[s * n + key], 1);
    g_col[pos] = col;
}

__device__ __forceinline__ float lrelu(float x) { return x > 0.f ? x : 0.2f * x; }

// ---------------- edge-softmax + aggregation: warp per (structure, dst-node),
// two relations per structure processed together (one on feat_src, one on feat_dst)
__global__ void k_agg(const float* __restrict__ fsrc, const float* __restrict__ fdst,
                      int n, int E) {
    int s = blockIdx.y;
    int warp = threadIdx.x >> 5, lane = threadIdx.x & 31;
    int node = blockIdx.x * 4 + warp;
    if (node >= n) return;
    int ra = (s < 2) ? s : s + 2;   // 0,1,4,5
    int rb = ra + 2;                // 2,3,6,7
    long idx = (long)s * n + node;
    int start = g_rowptr[idx];
    int end   = (idx + 1 < 4L * n) ? g_rowptr[idx + 1] : 4 * E;

    const float* ela = g_el + (long)ra * n;
    const float* elb = g_el + (long)rb * n;
    float era = g_er[(long)ra * n + node];
    float erb = g_er[(long)rb * n + node];

    float ma = -1e30f, mb = -1e30f;
    for (int k = start + lane; k < end; k += 32) {
        int c = __ldg(&g_col[k]);
        ma = fmaxf(ma, lrelu(ela[c] + era));
        mb = fmaxf(mb, lrelu(elb[c] + erb));
    }
    #pragma unroll
    for (int o = 16; o; o >>= 1) {
        ma = fmaxf(ma, __shfl_xor_sync(0xffffffffu, ma, o));
        mb = fmaxf(mb, __shfl_xor_sync(0xffffffffu, mb, o));
    }

    float4 acca = make_float4(0, 0, 0, 0), accb = make_float4(0, 0, 0, 0);
    float dena = 0.f, denb = 0.f;
    const float4* fs4 = (const float4*)fsrc;
    const float4* fd4 = (const float4*)fdst;

    for (int base = start; base < end; base += 32) {
        int k = base + lane;
        int c = 0; float wa = 0.f, wb = 0.f;
        if (k < end) {
            c = __ldg(&g_col[k]);
            wa = __expf(lrelu(ela[c] + era) - ma);
            wb = __expf(lrelu(elb[c] + erb) - mb);
        }
        int num = min(32, end - base);
        for (int j = 0; j < num; j++) {
            float waj = __shfl_sync(0xffffffffu, wa, j);
            float wbj = __shfl_sync(0xffffffffu, wb, j);
            int   cj  = __shfl_sync(0xffffffffu, c,  j);
            float4 xa = fs4[(long)cj * 32 + lane];
            float4 xb = fd4[(long)cj * 32 + lane];
            acca.x += waj * xa.x; acca.y += waj * xa.y; acca.z += waj * xa.z; acca.w += waj * xa.w;
            accb.x += wbj * xb.x; accb.y += wbj * xb.y; accb.z += wbj * xb.z; accb.w += wbj * xb.w;
            dena += waj; denb += wbj;
        }
    }
    float inva = 1.0f / fmaxf(dena, 1e-9f);
    float invb = 1.0f / fmaxf(denb, 1e-9f);
    float4 ya = make_float4(acca.x * inva, acca.y * inva, acca.z * inva, acca.w * inva);
    float4 yb = make_float4(accb.x * invb, accb.y * invb, accb.z * invb, accb.w * invb);
    __stcs(((float4*)g_Y) + ((long)ra * n + node) * 32 + lane, ya);
    __stcs(((float4*)g_Y) + ((long)rb * n + node) * 32 + lane, yb);
}

// ---------------- out = sum_r lam[r/2] * Y_r @ W_r + 2*(sum lam)*feat_dst + bias-combo
__global__ __launch_bounds__(256) void k_gemm(const float* __restrict__ W,
                                              const float* __restrict__ lam,
                                              const float* __restrict__ bias,
                                              const float* __restrict__ fdst,
                                              float* __restrict__ out, int n) {
    __shared__ float As[16][128];
    __shared__ float Bs[16][132];
    int tid = threadIdx.x;
    int tx = tid & 15, ty = tid >> 4;
    int row0 = blockIdx.x * 128;
    float acc[8][8];
    #pragma unroll
    for (int i = 0; i < 8; i++)
        #pragma unroll
        for (int j = 0; j < 8; j++) acc[i][j] = 0.f;

    const float4* W4 = (const float4*)W;
    for (int r = 0; r < 8; r++) {
        float lr = lam[r >> 1];
        const float4* Yr4 = (const float4*)(g_Y + (long)r * n * DD);
        for (int kb = 0; kb < 128; kb += 16) {
            #pragma unroll
            for (int j = 0; j < 2; j++) {
                int idx4 = tid + j * 256;       // 0..511
                int m = idx4 >> 2;
                int kk4 = idx4 & 3;
                float4 v = make_float4(0, 0, 0, 0);
                if (row0 + m < n) v = Yr4[(long)(row0 + m) * 32 + (kb >> 2) + kk4];
                As[kk4 * 4 + 0][m] = v.x;
                As[kk4 * 4 + 1][m] = v.y;
                As[kk4 * 4 + 2][m] = v.z;
                As[kk4 * 4 + 3][m] = v.w;
            }
            #pragma unroll
            for (int j = 0; j < 2; j++) {
                int idx4 = tid + j * 256;       // 0..511
                int k = idx4 >> 5;
                int d4 = idx4 & 31;
                float4 w = W4[r * 4096 + (kb + k) * 32 + d4];
                *(float4*)&Bs[k][d4 * 4] = make_float4(w.x * lr, w.y * lr, w.z * lr, w.w * lr);
            }
            __syncthreads();
            #pragma unroll
            for (int k = 0; k < 16; k++) {
                float a[8], b[8];
                #pragma unroll
                for (int i = 0; i < 8; i++) a[i] = As[k][ty * 8 + i];
                #pragma unroll
                for (int j = 0; j < 8; j++) b[j] = Bs[k][tx * 8 + j];
                #pragma unroll
                for (int i = 0; i < 8; i++)
                    #pragma unroll
                    for (int j = 0; j < 8; j++) acc[i][j] += a[i] * b[j];
            }
            __syncthreads();
        }
    }

    float cdst = 2.0f * (lam[0] + lam[1] + lam[2] + lam[3]);
    float bc[8];
    #pragma unroll
    for (int j = 0; j < 8; j++) {
        int d = tx * 8 + j;
        float sb = 0.f;
        #pragma unroll
        for (int t = 0; t < 4; t++)
            sb += lam[t] * (bias[(2 * t) * DD + d] + bias[(2 * t + 1) * DD + d]);
        bc[j] = sb;
    }
    #pragma unroll
    for (int i = 0; i < 8; i++) {
        int row = row0 + ty * 8 + i;
        if (row >= n) break;
        #pragma unroll
        for (int j = 0; j < 8; j++) {
            int d = tx * 8 + j;
            out[(long)row * DD + d] = acc[i][j] + cdst * fdst[(long)row * DD + d] + bc[j];
        }
    }
}

extern "C" void kernel_launch(void* const* d_in, const int* in_sizes, int n_in,
                              void* d_out, int out_size) {
    const float* fsrc = (const float*)d_in[0];
    const float* fdst = (const float*)d_in[1];
    const int*   isrc = (const int*)d_in[2];
    const int*   idst = (const int*)d_in[3];
    const int*   xsrc = (const int*)d_in[4];
    const int*   xdst = (const int*)d_in[5];
    const float* W    = (const float*)d_in[6];
    const float* al   = (const float*)d_in[7];
    const float* ar   = (const float*)d_in[8];
    const float* bias = (const float*)d_in[9];
    const float* lam  = (const float*)d_in[10];
    float* out = (float*)d_out;

    int n = in_sizes[0] / DD;
    int E = in_sizes[2];
    int len = 4 * n;
    int nb1 = (len + 1023) / 1024;

    k_prep<<<8, 128>>>(W, al, ar);
    k_elr<<<(n + 7) / 8, 256>>>(fsrc, fdst, n);
    k_zero<<<(len + 255) / 256, 256>>>(len);
    k_hist<<<(4 * E + 255) / 256, 256>>>(isrc, idst, xsrc, xdst, n, E);
    k_scan1<<<nb1, 1024>>>(len);
    k_scan2<<<1, 512>>>(nb1);
    k_scan3<<<nb1, 1024>>>(len);
    k_fill<<<(4 * E + 255) / 256, 256>>>(isrc, idst, xsrc, xdst, n, E);
    k_agg<<<dim3((n + 3) / 4, 4), 128>>>(fsrc, fdst, n, E);
    k_gemm<<<(n + 127) / 128, 256>>>(W, lam, bias, fdst, out, n);
}

// round 3
// speedup vs baseline: 1.6093x; 1.6093x over previous
#include <cuda_runtime.h>
#include <math.h>
#include <stdint.h>

#define MAXN 100000
#define MAXE 600000
#define DD 128

// ---------------- static device scratch (no allocations allowed) ----------------
__device__ float g_Y[8L * MAXN * DD];      // Y_r = S_r X_r
__device__ float g_Bt[8 * DD * DD];        // Bt[r][n][k] = lam[r/2] * W[r][k][n]
__device__ float g_el[8 * MAXN];
__device__ float g_er[8 * MAXN];
__device__ float g_wal[8 * DD];
__device__ float g_war[8 * DD];
__device__ int   g_cnt[4 * MAXN];
__device__ int   g_rowptr[4 * MAXN];
__device__ int   g_cursor[4 * MAXN];
__device__ int   g_col[4 * MAXE];
__device__ int   g_bsums[1024];
__device__ int   g_boffs[1024];

__device__ __forceinline__ float tf32rna(float x) {
    float y; asm("cvt.rna.tf32.f32 %0, %1;" : "=f"(y) : "f"(x)); return y;
}

// ---------------- wal_r = W_r @ al_r, war_r = W_r @ ar_r ----------------
__global__ void k_prep(const float* __restrict__ W, const float* __restrict__ al,
                       const float* __restrict__ ar) {
    int r = blockIdx.x, i = threadIdx.x;
    const float* Wr  = W + r * DD * DD + i * DD;
    const float* alr = al + r * DD;
    const float* arr = ar + r * DD;
    float sl = 0.f, sr = 0.f;
    #pragma unroll 8
    for (int j = 0; j < DD; j++) { float w = Wr[j]; sl += w * alr[j]; sr += w * arr[j]; }
    g_wal[r * DD + i] = sl;
    g_war[r * DD + i] = sr;
}

// ---------------- Bt[r][n][k] = lam[r/2] * W[r][k][n] ----------------
__global__ void k_prepBt(const float* __restrict__ W, const float* __restrict__ lam) {
    int t = blockIdx.x * 256 + threadIdx.x;      // 131072 total
    int r = t >> 14, rem = t & 16383;
    int nn = rem >> 7, kk = rem & 127;
    g_Bt[t] = lam[r >> 1] * W[(r * DD + kk) * DD + nn];
}

// ---------------- el[r][n], er[r][n] via 16 matvecs ----------------
__global__ void k_elr(const float* __restrict__ fsrc, const float* __restrict__ fdst, int n) {
    __shared__ float4 swal[8 * 32], swar[8 * 32];
    int tid = threadIdx.x;
    if (tid < 256) {
        swal[tid] = ((const float4*)g_wal)[tid];
        swar[tid] = ((const float4*)g_war)[tid];
    }
    __syncthreads();
    int warp = tid >> 5, lane = tid & 31;
    int node = blockIdx.x * 8 + warp;
    if (node >= n) return;
    float4 fs = ((const float4*)fsrc)[(long)node * 32 + lane];
    float4 fd = ((const float4*)fdst)[(long)node * 32 + lane];
    float p[16];
    #pragma unroll
    for (int r = 0; r < 8; r++) {
        float4 wl = swal[r * 32 + lane];
        float4 wr = swar[r * 32 + lane];
        bool useSrc = (r == 0 || r == 1 || r == 4 || r == 5);
        float4 x = useSrc ? fs : fd;
        p[r]     = x.x * wl.x + x.y * wl.y + x.z * wl.z + x.w * wl.w;
        p[8 + r] = fd.x * wr.x + fd.y * wr.y + fd.z * wr.z + fd.w * wr.w;
    }
    #pragma unroll
    for (int i = 0; i < 16; i++)
        #pragma unroll
        for (int o = 16; o; o >>= 1) p[i] += __shfl_xor_sync(0xffffffffu, p[i], o);
    if (lane == 0) {
        #pragma unroll
        for (int r = 0; r < 8; r++) {
            g_el[(long)r * n + node] = p[r];
            g_er[(long)r * n + node] = p[8 + r];
        }
    }
}

__global__ void k_zero(int len) {
    int i = blockIdx.x * blockDim.x + threadIdx.x;
    if (i < len) g_cnt[i] = 0;
}

__global__ void k_hist(const int* __restrict__ isrc, const int* __restrict__ idst,
                       const int* __restrict__ xsrc, const int* __restrict__ xdst,
                       int n, int E) {
    int t = blockIdx.x * blockDim.x + threadIdx.x;
    if (t >= 4 * E) return;
    int s = t / E, e = t - s * E;
    int key = (s == 0) ? idst[e] : (s == 1) ? xdst[e] : (s == 2) ? isrc[e] : xsrc[e];
    atomicAdd(&g_cnt[s * n + key], 1);
}

__global__ void k_scan1(int len) {
    __shared__ int sm[1024];
    int i = blockIdx.x * 1024 + threadIdx.x;
    int v = (i < len) ? g_cnt[i] : 0;
    sm[threadIdx.x] = v;
    __syncthreads();
    for (int off = 1; off < 1024; off <<= 1) {
        int t = (threadIdx.x >= off) ? sm[threadIdx.x - off] : 0;
        __syncthreads();
        sm[threadIdx.x] += t;
        __syncthreads();
    }
    if (i < len) g_rowptr[i] = sm[threadIdx.x];
    if (threadIdx.x == 1023) g_bsums[blockIdx.x] = sm[1023];
}

__global__ void k_scan2(int nb) {
    __shared__ int sm[512];
    int v = (threadIdx.x < nb) ? g_bsums[threadIdx.x] : 0;
    sm[threadIdx.x] = v;
    __syncthreads();
    for (int off = 1; off < 512; off <<= 1) {
        int t = (threadIdx.x >= off) ? sm[threadIdx.x - off] : 0;
        __syncthreads();
        sm[threadIdx.x] += t;
        __syncthreads();
    }
    if (threadIdx.x < nb) g_boffs[threadIdx.x] = sm[threadIdx.x] - v;
}

__global__ void k_scan3(int len) {
    int i = blockIdx.x * 1024 + threadIdx.x;
    if (i >= len) return;
    int excl = g_rowptr[i] - g_cnt[i] + g_boffs[blockIdx.x];
    g_rowptr[i] = excl;
    g_cursor[i] = excl;
}

__global__ void k_fill(const int* __restrict__ isrc, const int* __restrict__ idst,
                       const int* __restrict__ xsrc, const int* __restrict__ xdst,
                       int n, int E) {
    int t = blockIdx.x * blockDim.x + threadIdx.x;
    if (t >= 4 * E) return;
    int s = t / E, e = t - s * E;
    int key, col;
    if (s == 0)      { key = idst[e]; col = isrc[e]; }
    else if (s == 1) { key = xdst[e]; col = xsrc[e]; }
    else if (s == 2) { key = isrc[e]; col = idst[e]; }
    else             { key = xsrc[e]; col = xdst[e]; }
    int pos = atomicAdd(&g_cursor[s * n + key], 1);
    g_col[pos] = col;
}

__device__ __forceinline__ float lrelu(float x) { return x > 0.f ? x : 0.2f * x; }

// ---------------- edge-softmax + aggregation ----------------
__global__ void k_agg(const float* __restrict__ fsrc, const float* __restrict__ fdst,
                      int n, int E) {
    int s = blockIdx.y;
    int warp = threadIdx.x >> 5, lane = threadIdx.x & 31;
    int node = blockIdx.x * 4 + warp;
    if (node >= n) return;
    int ra = (s < 2) ? s : s + 2;
    int rb = ra + 2;
    long idx = (long)s * n + node;
    int start = g_rowptr[idx];
    int end   = (idx + 1 < 4L * n) ? g_rowptr[idx + 1] : 4 * E;

    const float* ela = g_el + (long)ra * n;
    const float* elb = g_el + (long)rb * n;
    float era = g_er[(long)ra * n + node];
    float erb = g_er[(long)rb * n + node];

    float ma = -1e30f, mb = -1e30f;
    for (int k = start + lane; k < end; k += 32) {
        int c = __ldg(&g_col[k]);
        ma = fmaxf(ma, lrelu(ela[c] + era));
        mb = fmaxf(mb, lrelu(elb[c] + erb));
    }
    #pragma unroll
    for (int o = 16; o; o >>= 1) {
        ma = fmaxf(ma, __shfl_xor_sync(0xffffffffu, ma, o));
        mb = fmaxf(mb, __shfl_xor_sync(0xffffffffu, mb, o));
    }

    float4 acca = make_float4(0, 0, 0, 0), accb = make_float4(0, 0, 0, 0);
    float dena = 0.f, denb = 0.f;
    const float4* fs4 = (const float4*)fsrc;
    const float4* fd4 = (const float4*)fdst;

    for (int base = start; base < end; base += 32) {
        int k = base + lane;
        int c = 0; float wa = 0.f, wb = 0.f;
        if (k < end) {
            c = __ldg(&g_col[k]);
            wa = __expf(lrelu(ela[c] + era) - ma);
            wb = __expf(lrelu(elb[c] + erb) - mb);
        }
        int num = min(32, end - base);
        for (int j = 0; j < num; j++) {
            float waj = __shfl_sync(0xffffffffu, wa, j);
            float wbj = __shfl_sync(0xffffffffu, wb, j);
            int   cj  = __shfl_sync(0xffffffffu, c,  j);
            float4 xa = fs4[(long)cj * 32 + lane];
            float4 xb = fd4[(long)cj * 32 + lane];
            acca.x += waj * xa.x; acca.y += waj * xa.y; acca.z += waj * xa.z; acca.w += waj * xa.w;
            accb.x += wbj * xb.x; accb.y += wbj * xb.y; accb.z += wbj * xb.z; accb.w += wbj * xb.w;
            dena += waj; denb += wbj;
        }
    }
    float inva = 1.0f / fmaxf(dena, 1e-9f);
    float invb = 1.0f / fmaxf(denb, 1e-9f);
    float4 ya = make_float4(acca.x * inva, acca.y * inva, acca.z * inva, acca.w * inva);
    float4 yb = make_float4(accb.x * invb, accb.y * invb, accb.z * invb, accb.w * invb);
    __stcs(((float4*)g_Y) + ((long)ra * n + node) * 32 + lane, ya);
    __stcs(((float4*)g_Y) + ((long)rb * n + node) * 32 + lane, yb);
}

// =================== mma.sync tf32 fused GEMM ===================
// out[M,128] = concatK_r(Y_r) @ concatK_r(Bt_r^T) + cdst*fdst + bc
// CTA tile 128x128, K=1024 in 32 chunks of 32. 8 warps, warp tile 64x32.
__device__ __forceinline__ void mma_tf32(float* c, const uint32_t* a, const uint32_t* b) {
    asm volatile(
        "mma.sync.aligned.m16n8k8.row.col.f32.tf32.tf32.f32 "
        "{%0,%1,%2,%3}, {%4,%5,%6,%7}, {%8,%9}, {%0,%1,%2,%3};"
        : "+f"(c[0]), "+f"(c[1]), "+f"(c[2]), "+f"(c[3])
        : "r"(a[0]), "r"(a[1]), "r"(a[2]), "r"(a[3]), "r"(b[0]), "r"(b[1]));
}

__global__ void __launch_bounds__(256, 2) k_gemm_mma(
    const float* __restrict__ lam, const float* __restrict__ bias,
    const float* __restrict__ fdst, float* __restrict__ out, int n) {
    __shared__ float As[128][36];   // [m][k], pad 4 -> conflict-free frag LDS
    __shared__ float Bs[128][36];   // [n][k]
    __shared__ float bcs[128];

    int tid = threadIdx.x, wid = tid >> 5, lane = tid & 31;
    int wm = wid & 1, wn = wid >> 1;          // warp tile: (wm*64, wn*32)
    int row0 = blockIdx.x * 128;
    int g = lane >> 2, q = lane & 3;

    if (tid < 128) {
        float s = 0.f;
        #pragma unroll
        for (int t = 0; t < 4; t++)
            s += lam[t] * (bias[(2 * t) * DD + tid] + bias[(2 * t + 1) * DD + tid]);
        bcs[tid] = s;
    }

    float acc[4][4][4];
    #pragma unroll
    for (int i = 0; i < 4; i++)
        #pragma unroll
        for (int j = 0; j < 4; j++)
            #pragma unroll
            for (int t = 0; t < 4; t++) acc[i][j][t] = 0.f;

    const float4* Y4  = (const float4*)g_Y;
    const float4* Bt4 = (const float4*)g_Bt;

    #pragma unroll 1
    for (int c = 0; c < 32; c++) {
        int r = c >> 2;
        int kq4 = (c & 3) * 8;                 // float4 offset within 128-K relation row
        __syncthreads();
        #pragma unroll
        for (int i = 0; i < 4; i++) {          // A: 1024 float4
            int idx = tid + i * 256;
            int row = idx >> 3, c4 = idx & 7;
            float4 v = make_float4(0, 0, 0, 0);
            int gr = row0 + row;
            if (gr < n) v = Y4[((long)r * n + gr) * 32 + kq4 + c4];
            v.x = tf32rna(v.x); v.y = tf32rna(v.y); v.z = tf32rna(v.z); v.w = tf32rna(v.w);
            *(float4*)&As[row][c4 * 4] = v;
        }
        #pragma unroll
        for (int i = 0; i < 4; i++) {          // B: 1024 float4
            int idx = tid + i * 256;
            int row = idx >> 3, c4 = idx & 7;
            float4 v = Bt4[((long)r * DD + row) * 32 + kq4 + c4];
            v.x = tf32rna(v.x); v.y = tf32rna(v.y); v.z = tf32rna(v.z); v.w = tf32rna(v.w);
            *(float4*)&Bs[row][c4 * 4] = v;
        }
        __syncthreads();
        #pragma unroll
        for (int ks = 0; ks < 4; ks++) {
            int kb = ks * 8;
            uint32_t a[4][4], b[4][2];
            #pragma unroll
            for (int mf = 0; mf < 4; mf++) {
                int m = wm * 64 + mf * 16;
                a[mf][0] = __float_as_uint(As[m + g][kb + q]);
                a[mf][1] = __float_as_uint(As[m + g + 8][kb + q]);
                a[mf][2] = __float_as_uint(As[m + g][kb + q + 4]);
                a[mf][3] = __float_as_uint(As[m + g + 8][kb + q + 4]);
            }
            #pragma unroll
            for (int nf = 0; nf < 4; nf++) {
                int nn = wn * 32 + nf * 8 + g;
                b[nf][0] = __float_as_uint(Bs[nn][kb + q]);
                b[nf][1] = __float_as_uint(Bs[nn][kb + q + 4]);
            }
            #pragma unroll
            for (int mf = 0; mf < 4; mf++)
                #pragma unroll
                for (int nf = 0; nf < 4; nf++)
                    mma_tf32(acc[mf][nf], a[mf], b[nf]);
        }
    }
    __syncthreads();

    float cdst = 2.0f * (__ldg(&lam[0]) + __ldg(&lam[1]) + __ldg(&lam[2]) + __ldg(&lam[3]));
    float2* out2 = (float2*)out;
    const float2* fd2 = (const float2*)fdst;
    #pragma unroll
    for (int mf = 0; mf < 4; mf++) {
        #pragma unroll
        for (int half = 0; half < 2; half++) {
            int row = row0 + wm * 64 + mf * 16 + g + half * 8;
            if (row >= n) continue;
            #pragma unroll
            for (int nf = 0; nf < 4; nf++) {
                int col = wn * 32 + nf * 8 + 2 * q;
                float2 fd = fd2[(long)row * 64 + (col >> 1)];
                float c0 = acc[mf][nf][half * 2 + 0];
                float c1 = acc[mf][nf][half * 2 + 1];
                float2 o;
                o.x = c0 + cdst * fd.x + bcs[col];
                o.y = c1 + cdst * fd.y + bcs[col + 1];
                out2[(long)row * 64 + (col >> 1)] = o;
            }
        }
    }
}

extern "C" void kernel_launch(void* const* d_in, const int* in_sizes, int n_in,
                              void* d_out, int out_size) {
    const float* fsrc = (const float*)d_in[0];
    const float* fdst = (const float*)d_in[1];
    const int*   isrc = (const int*)d_in[2];
    const int*   idst = (const int*)d_in[3];
    const int*   xsrc = (const int*)d_in[4];
    const int*   xdst = (const int*)d_in[5];
    const float* W    = (const float*)d_in[6];
    const float* al   = (const float*)d_in[7];
    const float* ar   = (const float*)d_in[8];
    const float* bias = (const float*)d_in[9];
    const float* lam  = (const float*)d_in[10];
    float* out = (float*)d_out;

    int n = in_sizes[0] / DD;
    int E = in_sizes[2];
    int len = 4 * n;
    int nb1 = (len + 1023) / 1024;

    k_prep<<<8, 128>>>(W, al, ar);
    k_prepBt<<<512, 256>>>(W, lam);
    k_elr<<<(n + 7) / 8, 256>>>(fsrc, fdst, n);
    k_zero<<<(len + 255) / 256, 256>>>(len);
    k_hist<<<(4 * E + 255) / 256, 256>>>(isrc, idst, xsrc, xdst, n, E);
    k_scan1<<<nb1, 1024>>>(len);
    k_scan2<<<1, 512>>>(nb1);
    k_scan3<<<nb1, 1024>>>(len);
    k_fill<<<(4 * E + 255) / 256, 256>>>(isrc, idst, xsrc, xdst, n, E);
    k_agg<<<dim3((n + 3) / 4, 4), 128>>>(fsrc, fdst, n, E);
    k_gemm_mma<<<(n + 127) / 128, 256>>>(lam, bias, fdst, out, n);
}

// round 4
// speedup vs baseline: 1.8803x; 1.1684x over previous
#include <cuda_runtime.h>
#include <math.h>
#include <stdint.h>

#define MAXN 100000
#define NPAD 100096            // padded row-count stride for g_Y (last GEMM tile reads in-bounds)
#define MAXE 600000
#define DD 128

// ---------------- static device scratch (no allocations allowed) ----------------
__device__ float g_Y[8L * NPAD * DD];      // Y_r = S_r X_r  (tf32-rounded at store)
__device__ float g_Bt[8 * DD * DD];        // Bt[r][n][k] = tf32(lam[r/2] * W[r][k][n])
__device__ float g_el[8 * MAXN];
__device__ float g_er[8 * MAXN];
__device__ float g_wal[8 * DD];
__device__ float g_war[8 * DD];
__device__ int   g_cnt[4 * MAXN];
__device__ int   g_rowptr[4 * MAXN];
__device__ int   g_cursor[4 * MAXN];
__device__ int   g_col[4 * MAXE];
__device__ int   g_bsums[1024];
__device__ int   g_boffs[1024];

__device__ __forceinline__ float tf32rna(float x) {
    float y; asm("cvt.rna.tf32.f32 %0, %1;" : "=f"(y) : "f"(x)); return y;
}
__device__ __forceinline__ uint32_t smem_u32(const void* p) {
    uint32_t a;
    asm("{ .reg .u64 t; cvta.to.shared.u64 t, %1; cvt.u32.u64 %0, t; }" : "=r"(a) : "l"(p));
    return a;
}
__device__ __forceinline__ void cp16(uint32_t dst, const void* src) {
    asm volatile("cp.async.ca.shared.global [%0], [%1], 16;" :: "r"(dst), "l"(src));
}
#define CP_COMMIT() asm volatile("cp.async.commit_group;" ::: "memory")
#define CP_WAIT(N)  asm volatile("cp.async.wait_group %0;" :: "n"(N) : "memory")

// ---------------- prep: wal/war dots + Bt transpose-scale ----------------
__global__ void k_prep2(const float* __restrict__ W, const float* __restrict__ al,
                        const float* __restrict__ ar, const float* __restrict__ lam) {
    int r = blockIdx.x, t = threadIdx.x;
    if (t < 128) {
        const float* Wr  = W + r * DD * DD + t * DD;
        const float* alr = al + r * DD;
        const float* arr = ar + r * DD;
        float sl = 0.f, sr = 0.f;
        #pragma unroll 8
        for (int j = 0; j < DD; j++) { float w = Wr[j]; sl += w * alr[j]; sr += w * arr[j]; }
        g_wal[r * DD + t] = sl;
        g_war[r * DD + t] = sr;
    }
    float lr = lam[r >> 1];
    for (int i = t; i < DD * DD; i += 256) {
        int nn = i >> 7, kk = i & 127;
        g_Bt[r * DD * DD + i] = tf32rna(lr * W[(r * DD + kk) * DD + nn]);
    }
}

// ---------------- el[r][n], er[r][n] via 16 matvecs ----------------
__global__ void k_elr(const float* __restrict__ fsrc, const float* __restrict__ fdst, int n) {
    __shared__ float4 swal[8 * 32], swar[8 * 32];
    int tid = threadIdx.x;
    if (tid < 256) {
        swal[tid] = ((const float4*)g_wal)[tid];
        swar[tid] = ((const float4*)g_war)[tid];
    }
    __syncthreads();
    int warp = tid >> 5, lane = tid & 31;
    int node = blockIdx.x * 8 + warp;
    if (node >= n) return;
    float4 fs = ((const float4*)fsrc)[(long)node * 32 + lane];
    float4 fd = ((const float4*)fdst)[(long)node * 32 + lane];
    float p[16];
    #pragma unroll
    for (int r = 0; r < 8; r++) {
        float4 wl = swal[r * 32 + lane];
        float4 wr = swar[r * 32 + lane];
        bool useSrc = (r == 0 || r == 1 || r == 4 || r == 5);
        float4 x = useSrc ? fs : fd;
        p[r]     = x.x * wl.x + x.y * wl.y + x.z * wl.z + x.w * wl.w;
        p[8 + r] = fd.x * wr.x + fd.y * wr.y + fd.z * wr.z + fd.w * wr.w;
    }
    #pragma unroll
    for (int i = 0; i < 16; i++)
        #pragma unroll
        for (int o = 16; o; o >>= 1) p[i] += __shfl_xor_sync(0xffffffffu, p[i], o);
    if (lane == 0) {
        #pragma unroll
        for (int r = 0; r < 8; r++) {
            g_el[(long)r * n + node] = p[r];
            g_er[(long)r * n + node] = p[8 + r];
        }
    }
}

__global__ void k_zero(int len) {
    int i = blockIdx.x * blockDim.x + threadIdx.x;
    if (i < len) g_cnt[i] = 0;
}

__global__ void k_hist(const int* __restrict__ isrc, const int* __restrict__ idst,
                       const int* __restrict__ xsrc, const int* __restrict__ xdst,
                       int n, int E) {
    int t = blockIdx.x * blockDim.x + threadIdx.x;
    if (t >= 4 * E) return;
    int s = t / E, e = t - s * E;
    int key = (s == 0) ? idst[e] : (s == 1) ? xdst[e] : (s == 2) ? isrc[e] : xsrc[e];
    atomicAdd(&g_cnt[s * n + key], 1);
}

__global__ void k_scan1(int len) {
    __shared__ int sm[1024];
    int i = blockIdx.x * 1024 + threadIdx.x;
    int v = (i < len) ? g_cnt[i] : 0;
    sm[threadIdx.x] = v;
    __syncthreads();
    for (int off = 1; off < 1024; off <<= 1) {
        int t = (threadIdx.x >= off) ? sm[threadIdx.x - off] : 0;
        __syncthreads();
        sm[threadIdx.x] += t;
        __syncthreads();
    }
    if (i < len) g_rowptr[i] = sm[threadIdx.x];
    if (threadIdx.x == 1023) g_bsums[blockIdx.x] = sm[1023];
}

__global__ void k_scan2(int nb) {
    __shared__ int sm[512];
    int v = (threadIdx.x < nb) ? g_bsums[threadIdx.x] : 0;
    sm[threadIdx.x] = v;
    __syncthreads();
    for (int off = 1; off < 512; off <<= 1) {
        int t = (threadIdx.x >= off) ? sm[threadIdx.x - off] : 0;
        __syncthreads();
        sm[threadIdx.x] += t;
        __syncthreads();
    }
    if (threadIdx.x < nb) g_boffs[threadIdx.x] = sm[threadIdx.x] - v;
}

__global__ void k_scan3(int len) {
    int i = blockIdx.x * 1024 + threadIdx.x;
    if (i >= len) return;
    int excl = g_rowptr[i] - g_cnt[i] + g_boffs[blockIdx.x];
    g_rowptr[i] = excl;
    g_cursor[i] = excl;
}

__global__ void k_fill(const int* __restrict__ isrc, const int* __restrict__ idst,
                       const int* __restrict__ xsrc, const int* __restrict__ xdst,
                       int n, int E) {
    int t = blockIdx.x * blockDim.x + threadIdx.x;
    if (t >= 4 * E) return;
    int s = t / E, e = t - s * E;
    int key, col;
    if (s == 0)      { key = idst[e]; col = isrc[e]; }
    else if (s == 1) { key = xdst[e]; col = xsrc[e]; }
    else if (s == 2) { key = isrc[e]; col = idst[e]; }
    else             { key = xsrc[e]; col = xdst[e]; }
    int pos = atomicAdd(&g_cursor[s * n + key], 1);
    g_col[pos] = col;
}

__device__ __forceinline__ float lrelu(float x) { return x > 0.f ? x : 0.2f * x; }

// ---------------- edge-softmax (no max pass) + aggregation, 2-edge unrolled ----------------
__global__ void k_agg(const float* __restrict__ fsrc, const float* __restrict__ fdst,
                      int n, int E) {
    int s = blockIdx.y;
    int warp = threadIdx.x >> 5, lane = threadIdx.x & 31;
    int node = blockIdx.x * 4 + warp;
    if (node >= n) return;
    int ra = (s < 2) ? s : s + 2;
    int rb = ra + 2;
    long idx = (long)s * n + node;
    int start = g_rowptr[idx];
    int end   = (idx + 1 < 4L * n) ? g_rowptr[idx + 1] : 4 * E;

    const float* ela = g_el + (long)ra * n;
    const float* elb = g_el + (long)rb * n;
    float era = g_er[(long)ra * n + node];
    float erb = g_er[(long)rb * n + node];

    float4 acca = make_float4(0, 0, 0, 0), accb = make_float4(0, 0, 0, 0);
    float dena = 0.f, denb = 0.f;
    const float4* fs4 = (const float4*)fsrc;
    const float4* fd4 = (const float4*)fdst;

    for (int base = start; base < end; base += 32) {
        int k = base + lane;
        int c = 0; float wa = 0.f, wb = 0.f;
        if (k < end) {
            c = __ldg(&g_col[k]);
            wa = __expf(lrelu(ela[c] + era));
            wb = __expf(lrelu(elb[c] + erb));
        }
        dena += wa; denb += wb;
        int num = min(32, end - base);
        int j = 0;
        for (; j + 1 < num; j += 2) {
            int   c0  = __shfl_sync(0xffffffffu, c,  j);
            float wa0 = __shfl_sync(0xffffffffu, wa, j);
            float wb0 = __shfl_sync(0xffffffffu, wb, j);
            int   c1  = __shfl_sync(0xffffffffu, c,  j + 1);
            float wa1 = __shfl_sync(0xffffffffu, wa, j + 1);
            float wb1 = __shfl_sync(0xffffffffu, wb, j + 1);
            float4 xa0 = fs4[(long)c0 * 32 + lane];
            float4 xb0 = fd4[(long)c0 * 32 + lane];
            float4 xa1 = fs4[(long)c1 * 32 + lane];
            float4 xb1 = fd4[(long)c1 * 32 + lane];
            acca.x += wa0 * xa0.x + wa1 * xa1.x;
            acca.y += wa0 * xa0.y + wa1 * xa1.y;
            acca.z += wa0 * xa0.z + wa1 * xa1.z;
            acca.w += wa0 * xa0.w + wa1 * xa1.w;
            accb.x += wb0 * xb0.x + wb1 * xb1.x;
            accb.y += wb0 * xb0.y + wb1 * xb1.y;
            accb.z += wb0 * xb0.z + wb1 * xb1.z;
            accb.w += wb0 * xb0.w + wb1 * xb1.w;
        }
        if (j < num) {
            int   c0  = __shfl_sync(0xffffffffu, c,  j);
            float wa0 = __shfl_sync(0xffffffffu, wa, j);
            float wb0 = __shfl_sync(0xffffffffu, wb, j);
            float4 xa0 = fs4[(long)c0 * 32 + lane];
            float4 xb0 = fd4[(long)c0 * 32 + lane];
            acca.x += wa0 * xa0.x; acca.y += wa0 * xa0.y;
            acca.z += wa0 * xa0.z; acca.w += wa0 * xa0.w;
            accb.x += wb0 * xb0.x; accb.y += wb0 * xb0.y;
            accb.z += wb0 * xb0.z; accb.w += wb0 * xb0.w;
        }
    }
    #pragma unroll
    for (int o = 16; o; o >>= 1) {
        dena += __shfl_xor_sync(0xffffffffu, dena, o);
        denb += __shfl_xor_sync(0xffffffffu, denb, o);
    }
    float inva = 1.0f / fmaxf(dena, 1e-9f);
    float invb = 1.0f / fmaxf(denb, 1e-9f);
    float4 ya = make_float4(tf32rna(acca.x * inva), tf32rna(acca.y * inva),
                            tf32rna(acca.z * inva), tf32rna(acca.w * inva));
    float4 yb = make_float4(tf32rna(accb.x * invb), tf32rna(accb.y * invb),
                            tf32rna(accb.z * invb), tf32rna(accb.w * invb));
    __stcs(((float4*)g_Y) + ((long)ra * NPAD + node) * 32 + lane, ya);
    __stcs(((float4*)g_Y) + ((long)rb * NPAD + node) * 32 + lane, yb);
}

// =================== mma.sync tf32 fused GEMM, cp.async double-buffered ===================
// smem floats: As[2][128][36]=9216 | Bs[2][128][36]=9216 | bcs[128]
#define SM_AS 0
#define SM_BS 9216
#define SM_BC 18432
#define GEMM_SMEM_BYTES ((18432 + 128) * 4)

__device__ __forceinline__ void mma_tf32(float* c, const uint32_t* a, const uint32_t* b) {
    asm volatile(
        "mma.sync.aligned.m16n8k8.row.col.f32.tf32.tf32.f32 "
        "{%0,%1,%2,%3}, {%4,%5,%6,%7}, {%8,%9}, {%0,%1,%2,%3};"
        : "+f"(c[0]), "+f"(c[1]), "+f"(c[2]), "+f"(c[3])
        : "r"(a[0]), "r"(a[1]), "r"(a[2]), "r"(a[3]), "r"(b[0]), "r"(b[1]));
}

__global__ void __launch_bounds__(256, 2) k_gemm_mma(
    const float* __restrict__ lam, const float* __restrict__ bias,
    const float* __restrict__ fdst, float* __restrict__ out, int n) {
    extern __shared__ float sm[];
    float* As = sm + SM_AS;
    float* Bs = sm + SM_BS;
    float* bcs = sm + SM_BC;
    uint32_t sm_base = smem_u32(sm);

    int tid = threadIdx.x, wid = tid >> 5, lane = tid & 31;
    int wm = wid & 1, wn = wid >> 1;
    int row0 = blockIdx.x * 128;
    int g = lane >> 2, q = lane & 3;

    if (tid < 128) {
        float s = 0.f;
        #pragma unroll
        for (int t = 0; t < 4; t++)
            s += lam[t] * (bias[(2 * t) * DD + tid] + bias[(2 * t + 1) * DD + tid]);
        bcs[tid] = s;
    }

    float acc[4][4][4];
    #pragma unroll
    for (int i = 0; i < 4; i++)
        #pragma unroll
        for (int j = 0; j < 4; j++)
            #pragma unroll
            for (int t = 0; t < 4; t++) acc[i][j][t] = 0.f;

    const float4* Y4  = (const float4*)g_Y;
    const float4* Bt4 = (const float4*)g_Bt;

    int ldr = tid >> 3, ldc4 = tid & 7;     // each thread: rows ldr, ldr+32, ldr+64, ldr+96

    // issue(c, buf): 4 A cps + 4 B cps for 32-K chunk c
    auto issue = [&](int c, int buf) {
        int r = c >> 2;
        int kq4 = (c & 3) * 8;
        const float4* ys = Y4 + ((long)r * NPAD + row0 + ldr) * 32 + kq4 + ldc4;
        const float4* bs = Bt4 + ((long)r * DD + ldr) * 32 + kq4 + ldc4;
        uint32_t ad = sm_base + (uint32_t)(SM_AS + buf * 4608 + ldr * 36 + ldc4 * 4) * 4u;
        uint32_t bd = sm_base + (uint32_t)(SM_BS + buf * 4608 + ldr * 36 + ldc4 * 4) * 4u;
        #pragma unroll
        for (int i = 0; i < 4; i++) {
            cp16(ad + (uint32_t)(i * 32 * 36 * 4), ys + (long)i * 32 * 32);
            cp16(bd + (uint32_t)(i * 32 * 36 * 4), bs + i * 32 * 32);
        }
        CP_COMMIT();
    };

    issue(0, 0);
    #pragma unroll 1
    for (int c = 0; c < 32; c++) {
        int buf = c & 1;
        if (c < 31) { issue(c + 1, buf ^ 1); CP_WAIT(1); }
        else        { CP_WAIT(0); }
        __syncthreads();
        const float* Ab = As + buf * 4608;
        const float* Bb = Bs + buf * 4608;
        #pragma unroll
        for (int ks = 0; ks < 4; ks++) {
            int kb = ks * 8;
            uint32_t a[4][4], b[4][2];
            #pragma unroll
            for (int mf = 0; mf < 4; mf++) {
                int m = wm * 64 + mf * 16;
                a[mf][0] = __float_as_uint(Ab[(m + g) * 36 + kb + q]);
                a[mf][1] = __float_as_uint(Ab[(m + g + 8) * 36 + kb + q]);
                a[mf][2] = __float_as_uint(Ab[(m + g) * 36 + kb + q + 4]);
                a[mf][3] = __float_as_uint(Ab[(m + g + 8) * 36 + kb + q + 4]);
            }
            #pragma unroll
            for (int nf = 0; nf < 4; nf++) {
                int nn = wn * 32 + nf * 8 + g;
                b[nf][0] = __float_as_uint(Bb[nn * 36 + kb + q]);
                b[nf][1] = __float_as_uint(Bb[nn * 36 + kb + q + 4]);
            }
            #pragma unroll
            for (int mf = 0; mf < 4; mf++)
                #pragma unroll
                for (int nf = 0; nf < 4; nf++)
                    mma_tf32(acc[mf][nf], a[mf], b[nf]);
        }
        __syncthreads();
    }

    float cdst = 2.0f * (__ldg(&lam[0]) + __ldg(&lam[1]) + __ldg(&lam[2]) + __ldg(&lam[3]));
    float2* out2 = (float2*)out;
    const float2* fd2 = (const float2*)fdst;
    #pragma unroll
    for (int mf = 0; mf < 4; mf++) {
        #pragma unroll
        for (int half = 0; half < 2; half++) {
            int row = row0 + wm * 64 + mf * 16 + g + half * 8;
            if (row >= n) continue;
            #pragma unroll
            for (int nf = 0; nf < 4; nf++) {
                int col = wn * 32 + nf * 8 + 2 * q;
                float2 fd = fd2[(long)row * 64 + (col >> 1)];
                float c0 = acc[mf][nf][half * 2 + 0];
                float c1 = acc[mf][nf][half * 2 + 1];
                float2 o;
                o.x = c0 + cdst * fd.x + bcs[col];
                o.y = c1 + cdst * fd.y + bcs[col + 1];
                out2[(long)row * 64 + (col >> 1)] = o;
            }
        }
    }
}

extern "C" void kernel_launch(void* const* d_in, const int* in_sizes, int n_in,
                              void* d_out, int out_size) {
    const float* fsrc = (const float*)d_in[0];
    const float* fdst = (const float*)d_in[1];
    const int*   isrc = (const int*)d_in[2];
    const int*   idst = (const int*)d_in[3];
    const int*   xsrc = (const int*)d_in[4];
    const int*   xdst = (const int*)d_in[5];
    const float* W    = (const float*)d_in[6];
    const float* al   = (const float*)d_in[7];
    const float* ar   = (const float*)d_in[8];
    const float* bias = (const float*)d_in[9];
    const float* lam  = (const float*)d_in[10];
    float* out = (float*)d_out;

    int n = in_sizes[0] / DD;
    int E = in_sizes[2];
    int len = 4 * n;
    int nb1 = (len + 1023) / 1024;

    static int configured = 0;
    if (!configured) {
        cudaFuncSetAttribute(k_gemm_mma, cudaFuncAttributeMaxDynamicSharedMemorySize,
                             GEMM_SMEM_BYTES);
        configured = 1;
    }

    k_prep2<<<8, 256>>>(W, al, ar, lam);
    k_elr<<<(n + 7) / 8, 256>>>(fsrc, fdst, n);
    k_zero<<<(len + 255) / 256, 256>>>(len);
    k_hist<<<(4 * E + 255) / 256, 256>>>(isrc, idst, xsrc, xdst, n, E);
    k_scan1<<<nb1, 1024>>>(len);
    k_scan2<<<1, 512>>>(nb1);
    k_scan3<<<nb1, 1024>>>(len);
    k_fill<<<(4 * E + 255) / 256, 256>>>(isrc, idst, xsrc, xdst, n, E);
    k_agg<<<dim3((n + 3) / 4, 4), 128>>>(fsrc, fdst, n, E);
    k_gemm_mma<<<(n + 127) / 128, 256, GEMM_SMEM_BYTES>>>(lam, bias, fdst, out, n);
}

// round 5
// speedup vs baseline: 2.0754x; 1.1037x over previous
#include <cuda_runtime.h>
#include <cuda_bf16.h>
#include <math.h>
#include <stdint.h>

#define MAXN 100000
#define NPAD 100096            // padded row stride for g_Y (last GEMM tile reads in-bounds)
#define MAXE 600000
#define DD 128

// ---------------- static device scratch (no allocations allowed) ----------------
__device__ float g_Y[8L * NPAD * DD];            // Y_r = S_r X_r (tf32-rounded at store)
__device__ float g_Bt[8 * DD * DD];              // Bt[r][n][k] = tf32(lam[r/2] * W[r][k][n])
__device__ __nv_bfloat16 g_fsH[MAXN * DD];       // bf16 mirror of feat_src
__device__ __nv_bfloat16 g_fdH[MAXN * DD];       // bf16 mirror of feat_dst
__device__ float g_el[8 * MAXN];
__device__ float g_er[8 * MAXN];
__device__ float g_wal[8 * DD];
__device__ float g_war[8 * DD];
__device__ int   g_cnt[4 * MAXN];
__device__ int   g_rowptr[4 * MAXN];
__device__ int   g_cursor[4 * MAXN];
__device__ int   g_col[4 * MAXE];
__device__ int   g_bsums[1024];
__device__ int   g_boffs[1024];

__device__ __forceinline__ float tf32rna(float x) {
    float y; asm("cvt.rna.tf32.f32 %0, %1;" : "=f"(y) : "f"(x)); return y;
}
__device__ __forceinline__ uint32_t smem_u32(const void* p) {
    uint32_t a;
    asm("{ .reg .u64 t; cvta.to.shared.u64 t, %1; cvt.u32.u64 %0, t; }" : "=r"(a) : "l"(p));
    return a;
}
__device__ __forceinline__ void cp16(uint32_t dst, const void* src) {
    asm volatile("cp.async.ca.shared.global [%0], [%1], 16;" :: "r"(dst), "l"(src));
}
#define CP_COMMIT() asm volatile("cp.async.commit_group;" ::: "memory")
#define CP_WAIT(N)  asm volatile("cp.async.wait_group %0;" :: "n"(N) : "memory")

__device__ __forceinline__ float2 bf2f(uint32_t u) {
    __nv_bfloat162 h = *reinterpret_cast<__nv_bfloat162*>(&u);
    return __bfloat1622float2(h);
}

// ---------------- prep: wal/war dots + Bt transpose-scale ----------------
__global__ void k_prep2(const float* __restrict__ W, const float* __restrict__ al,
                        const float* __restrict__ ar, const float* __restrict__ lam) {
    int r = blockIdx.x, t = threadIdx.x;
    if (t < 128) {
        const float* Wr  = W + r * DD * DD + t * DD;
        const float* alr = al + r * DD;
        const float* arr = ar + r * DD;
        float sl = 0.f, sr = 0.f;
        #pragma unroll 8
        for (int j = 0; j < DD; j++) { float w = Wr[j]; sl += w * alr[j]; sr += w * arr[j]; }
        g_wal[r * DD + t] = sl;
        g_war[r * DD + t] = sr;
    }
    float lr = lam[r >> 1];
    for (int i = t; i < DD * DD; i += 256) {
        int nn = i >> 7, kk = i & 127;
        g_Bt[r * DD * DD + i] = tf32rna(lr * W[(r * DD + kk) * DD + nn]);
    }
}

// ---------------- el/er matvecs + bf16 feature mirrors ----------------
__global__ void k_elr(const float* __restrict__ fsrc, const float* __restrict__ fdst, int n) {
    __shared__ float4 swal[8 * 32], swar[8 * 32];
    int tid = threadIdx.x;
    if (tid < 256) {
        swal[tid] = ((const float4*)g_wal)[tid];
        swar[tid] = ((const float4*)g_war)[tid];
    }
    __syncthreads();
    int warp = tid >> 5, lane = tid & 31;
    int node = blockIdx.x * 8 + warp;
    if (node >= n) return;
    float4 fs = ((const float4*)fsrc)[(long)node * 32 + lane];
    float4 fd = ((const float4*)fdst)[(long)node * 32 + lane];

    // bf16 mirrors (same [node*128 + lane*4] layout)
    {
        __nv_bfloat162 a0 = __floats2bfloat162_rn(fs.x, fs.y);
        __nv_bfloat162 a1 = __floats2bfloat162_rn(fs.z, fs.w);
        __nv_bfloat162 b0 = __floats2bfloat162_rn(fd.x, fd.y);
        __nv_bfloat162 b1 = __floats2bfloat162_rn(fd.z, fd.w);
        uint2 ua, ub;
        ua.x = *reinterpret_cast<uint32_t*>(&a0); ua.y = *reinterpret_cast<uint32_t*>(&a1);
        ub.x = *reinterpret_cast<uint32_t*>(&b0); ub.y = *reinterpret_cast<uint32_t*>(&b1);
        ((uint2*)g_fsH)[(long)node * 32 + lane] = ua;
        ((uint2*)g_fdH)[(long)node * 32 + lane] = ub;
    }

    float p[16];
    #pragma unroll
    for (int r = 0; r < 8; r++) {
        float4 wl = swal[r * 32 + lane];
        float4 wr = swar[r * 32 + lane];
        bool useSrc = (r == 0 || r == 1 || r == 4 || r == 5);
        float4 x = useSrc ? fs : fd;
        p[r]     = x.x * wl.x + x.y * wl.y + x.z * wl.z + x.w * wl.w;
        p[8 + r] = fd.x * wr.x + fd.y * wr.y + fd.z * wr.z + fd.w * wr.w;
    }
    #pragma unroll
    for (int i = 0; i < 16; i++)
        #pragma unroll
        for (int o = 16; o; o >>= 1) p[i] += __shfl_xor_sync(0xffffffffu, p[i], o);
    if (lane == 0) {
        #pragma unroll
        for (int r = 0; r < 8; r++) {
            g_el[(long)r * n + node] = p[r];
            g_er[(long)r * n + node] = p[8 + r];
        }
    }
}

__global__ void k_zero(int len) {
    int i = blockIdx.x * blockDim.x + threadIdx.x;
    if (i < len) g_cnt[i] = 0;
}

__global__ void k_hist(const int* __restrict__ isrc, const int* __restrict__ idst,
                       const int* __restrict__ xsrc, const int* __restrict__ xdst,
                       int n, int E) {
    int t = blockIdx.x * blockDim.x + threadIdx.x;
    if (t >= 4 * E) return;
    int s = t / E, e = t - s * E;
    int key = (s == 0) ? idst[e] : (s == 1) ? xdst[e] : (s == 2) ? isrc[e] : xsrc[e];
    atomicAdd(&g_cnt[s * n + key], 1);
}

__global__ void k_scan1(int len) {
    __shared__ int sm[1024];
    int i = blockIdx.x * 1024 + threadIdx.x;
    int v = (i < len) ? g_cnt[i] : 0;
    sm[threadIdx.x] = v;
    __syncthreads();
    for (int off = 1; off < 1024; off <<= 1) {
        int t = (threadIdx.x >= off) ? sm[threadIdx.x - off] : 0;
        __syncthreads();
        sm[threadIdx.x] += t;
        __syncthreads();
    }
    if (i < len) g_rowptr[i] = sm[threadIdx.x];
    if (threadIdx.x == 1023) g_bsums[blockIdx.x] = sm[1023];
}

__global__ void k_scan2(int nb) {
    __shared__ int sm[512];
    int v = (threadIdx.x < nb) ? g_bsums[threadIdx.x] : 0;
    sm[threadIdx.x] = v;
    __syncthreads();
    for (int off = 1; off < 512; off <<= 1) {
        int t = (threadIdx.x >= off) ? sm[threadIdx.x - off] : 0;
        __syncthreads();
        sm[threadIdx.x] += t;
        __syncthreads();
    }
    if (threadIdx.x < nb) g_boffs[threadIdx.x] = sm[threadIdx.x] - v;
}

__global__ void k_scan3(int len) {
    int i = blockIdx.x * 1024 + threadIdx.x;
    if (i >= len) return;
    int excl = g_rowptr[i] - g_cnt[i] + g_boffs[blockIdx.x];
    g_rowptr[i] = excl;
    g_cursor[i] = excl;
}

__global__ void k_fill(const int* __restrict__ isrc, const int* __restrict__ idst,
                       const int* __restrict__ xsrc, const int* __restrict__ xdst,
                       int n, int E) {
    int t = blockIdx.x * blockDim.x + threadIdx.x;
    if (t >= 4 * E) return;
    int s = t / E, e = t - s * E;
    int key, col;
    if (s == 0)      { key = idst[e]; col = isrc[e]; }
    else if (s == 1) { key = xdst[e]; col = xsrc[e]; }
    else if (s == 2) { key = isrc[e]; col = idst[e]; }
    else             { key = xsrc[e]; col = xdst[e]; }
    int pos = atomicAdd(&g_cursor[s * n + key], 1);
    g_col[pos] = col;
}

__device__ __forceinline__ float lrelu(float x) { return x > 0.f ? x : 0.2f * x; }

// ---------------- edge-softmax (no max pass) + bf16 aggregation ----------------
__global__ void k_agg(int n, int E) {
    int s = blockIdx.y;
    int warp = threadIdx.x >> 5, lane = threadIdx.x & 31;
    int node = blockIdx.x * 4 + warp;
    if (node >= n) return;
    int ra = (s < 2) ? s : s + 2;
    int rb = ra + 2;
    long idx = (long)s * n + node;
    int start = g_rowptr[idx];
    int end   = (idx + 1 < 4L * n) ? g_rowptr[idx + 1] : 4 * E;

    const float* ela = g_el + (long)ra * n;
    const float* elb = g_el + (long)rb * n;
    float era = g_er[(long)ra * n + node];
    float erb = g_er[(long)rb * n + node];

    float4 acca = make_float4(0, 0, 0, 0), accb = make_float4(0, 0, 0, 0);
    float dena = 0.f, denb = 0.f;
    const uint2* fs2 = (const uint2*)g_fsH;
    const uint2* fd2 = (const uint2*)g_fdH;

    for (int base = start; base < end; base += 32) {
        int k = base + lane;
        int c = 0; float wa = 0.f, wb = 0.f;
        if (k < end) {
            c = __ldg(&g_col[k]);
            wa = __expf(lrelu(ela[c] + era));
            wb = __expf(lrelu(elb[c] + erb));
        }
        dena += wa; denb += wb;
        int num = min(32, end - base);
        int j = 0;
        for (; j + 1 < num; j += 2) {
            int   c0  = __shfl_sync(0xffffffffu, c,  j);
            float wa0 = __shfl_sync(0xffffffffu, wa, j);
            float wb0 = __shfl_sync(0xffffffffu, wb, j);
            int   c1  = __shfl_sync(0xffffffffu, c,  j + 1);
            float wa1 = __shfl_sync(0xffffffffu, wa, j + 1);
            float wb1 = __shfl_sync(0xffffffffu, wb, j + 1);
            uint2 ua0 = fs2[(long)c0 * 32 + lane];
            uint2 ub0 = fd2[(long)c0 * 32 + lane];
            uint2 ua1 = fs2[(long)c1 * 32 + lane];
            uint2 ub1 = fd2[(long)c1 * 32 + lane];
            float2 a00 = bf2f(ua0.x), a01 = bf2f(ua0.y);
            float2 b00 = bf2f(ub0.x), b01 = bf2f(ub0.y);
            float2 a10 = bf2f(ua1.x), a11 = bf2f(ua1.y);
            float2 b10 = bf2f(ub1.x), b11 = bf2f(ub1.y);
            acca.x += wa0 * a00.x + wa1 * a10.x;
            acca.y += wa0 * a00.y + wa1 * a10.y;
            acca.z += wa0 * a01.x + wa1 * a11.x;
            acca.w += wa0 * a01.y + wa1 * a11.y;
            accb.x += wb0 * b00.x + wb1 * b10.x;
            accb.y += wb0 * b00.y + wb1 * b10.y;
            accb.z += wb0 * b01.x + wb1 * b11.x;
            accb.w += wb0 * b01.y + wb1 * b11.y;
        }
        if (j < num) {
            int   c0  = __shfl_sync(0xffffffffu, c,  j);
            float wa0 = __shfl_sync(0xffffffffu, wa, j);
            float wb0 = __shfl_sync(0xffffffffu, wb, j);
            uint2 ua0 = fs2[(long)c0 * 32 + lane];
            uint2 ub0 = fd2[(long)c0 * 32 + lane];
            float2 a00 = bf2f(ua0.x), a01 = bf2f(ua0.y);
            float2 b00 = bf2f(ub0.x), b01 = bf2f(ub0.y);
            acca.x += wa0 * a00.x; acca.y += wa0 * a00.y;
            acca.z += wa0 * a01.x; acca.w += wa0 * a01.y;
            accb.x += wb0 * b00.x; accb.y += wb0 * b00.y;
            accb.z += wb0 * b01.x; accb.w += wb0 * b01.y;
        }
    }
    #pragma unroll
    for (int o = 16; o; o >>= 1) {
        dena += __shfl_xor_sync(0xffffffffu, dena, o);
        denb += __shfl_xor_sync(0xffffffffu, denb, o);
    }
    float inva = 1.0f / fmaxf(dena, 1e-9f);
    float invb = 1.0f / fmaxf(denb, 1e-9f);
    float4 ya = make_float4(tf32rna(acca.x * inva), tf32rna(acca.y * inva),
                            tf32rna(acca.z * inva), tf32rna(acca.w * inva));
    float4 yb = make_float4(tf32rna(accb.x * invb), tf32rna(accb.y * invb),
                            tf32rna(accb.z * invb), tf32rna(accb.w * invb));
    __stcs(((float4*)g_Y) + ((long)ra * NPAD + node) * 32 + lane, ya);
    __stcs(((float4*)g_Y) + ((long)rb * NPAD + node) * 32 + lane, yb);
}

// =================== mma.sync tf32 fused GEMM, cp.async double-buffered ===================
#define SM_AS 0
#define SM_BS 9216
#define SM_BC 18432
#define GEMM_SMEM_BYTES ((18432 + 128) * 4)

__device__ __forceinline__ void mma_tf32(float* c, const uint32_t* a, const uint32_t* b) {
    asm volatile(
        "mma.sync.aligned.m16n8k8.row.col.f32.tf32.tf32.f32 "
        "{%0,%1,%2,%3}, {%4,%5,%6,%7}, {%8,%9}, {%0,%1,%2,%3};"
        : "+f"(c[0]), "+f"(c[1]), "+f"(c[2]), "+f"(c[3])
        : "r"(a[0]), "r"(a[1]), "r"(a[2]), "r"(a[3]), "r"(b[0]), "r"(b[1]));
}

__global__ void __launch_bounds__(256, 2) k_gemm_mma(
    const float* __restrict__ lam, const float* __restrict__ bias,
    const float* __restrict__ fdst, float* __restrict__ out, int n) {
    extern __shared__ float sm[];
    float* As = sm + SM_AS;
    float* Bs = sm + SM_BS;
    float* bcs = sm + SM_BC;
    uint32_t sm_base = smem_u32(sm);

    int tid = threadIdx.x, wid = tid >> 5, lane = tid & 31;
    int wm = wid & 1, wn = wid >> 1;
    int row0 = blockIdx.x * 128;
    int g = lane >> 2, q = lane & 3;

    if (tid < 128) {
        float s = 0.f;
        #pragma unroll
        for (int t = 0; t < 4; t++)
            s += lam[t] * (bias[(2 * t) * DD + tid] + bias[(2 * t + 1) * DD + tid]);
        bcs[tid] = s;
    }

    float acc[4][4][4];
    #pragma unroll
    for (int i = 0; i < 4; i++)
        #pragma unroll
        for (int j = 0; j < 4; j++)
            #pragma unroll
            for (int t = 0; t < 4; t++) acc[i][j][t] = 0.f;

    const float4* Y4  = (const float4*)g_Y;
    const float4* Bt4 = (const float4*)g_Bt;

    int ldr = tid >> 3, ldc4 = tid & 7;

    auto issue = [&](int c, int buf) {
        int r = c >> 2;
        int kq4 = (c & 3) * 8;
        const float4* ys = Y4 + ((long)r * NPAD + row0 + ldr) * 32 + kq4 + ldc4;
        const float4* bs = Bt4 + ((long)r * DD + ldr) * 32 + kq4 + ldc4;
        uint32_t ad = sm_base + (uint32_t)(SM_AS + buf * 4608 + ldr * 36 + ldc4 * 4) * 4u;
        uint32_t bd = sm_base + (uint32_t)(SM_BS + buf * 4608 + ldr * 36 + ldc4 * 4) * 4u;
        #pragma unroll
        for (int i = 0; i < 4; i++) {
            cp16(ad + (uint32_t)(i * 32 * 36 * 4), ys + (long)i * 32 * 32);
            cp16(bd + (uint32_t)(i * 32 * 36 * 4), bs + i * 32 * 32);
        }
        CP_COMMIT();
    };

    issue(0, 0);
    #pragma unroll 1
    for (int c = 0; c < 32; c++) {
        int buf = c & 1;
        if (c < 31) { issue(c + 1, buf ^ 1); CP_WAIT(1); }
        else        { CP_WAIT(0); }
        __syncthreads();
        const float* Ab = As + buf * 4608;
        const float* Bb = Bs + buf * 4608;
        #pragma unroll
        for (int ks = 0; ks < 4; ks++) {
            int kb = ks * 8;
            uint32_t a[4][4], b[4][2];
            #pragma unroll
            for (int mf = 0; mf < 4; mf++) {
                int m = wm * 64 + mf * 16;
                a[mf][0] = __float_as_uint(Ab[(m + g) * 36 + kb + q]);
                a[mf][1] = __float_as_uint(Ab[(m + g + 8) * 36 + kb + q]);
                a[mf][2] = __float_as_uint(Ab[(m + g) * 36 + kb + q + 4]);
                a[mf][3] = __float_as_uint(Ab[(m + g + 8) * 36 + kb + q + 4]);
            }
            #pragma unroll
            for (int nf = 0; nf < 4; nf++) {
                int nn = wn * 32 + nf * 8 + g;
                b[nf][0] = __float_as_uint(Bb[nn * 36 + kb + q]);
                b[nf][1] = __float_as_uint(Bb[nn * 36 + kb + q + 4]);
            }
            #pragma unroll
            for (int mf = 0; mf < 4; mf++)
                #pragma unroll
                for (int nf = 0; nf < 4; nf++)
                    mma_tf32(acc[mf][nf], a[mf], b[nf]);
        }
        __syncthreads();
    }

    float cdst = 2.0f * (__ldg(&lam[0]) + __ldg(&lam[1]) + __ldg(&lam[2]) + __ldg(&lam[3]));
    float2* out2 = (float2*)out;
    const float2* fd2 = (const float2*)fdst;
    #pragma unroll
    for (int mf = 0; mf < 4; mf++) {
        #pragma unroll
        for (int half = 0; half < 2; half++) {
            int row = row0 + wm * 64 + mf * 16 + g + half * 8;
            if (row >= n) continue;
            #pragma unroll
            for (int nf = 0; nf < 4; nf++) {
                int col = wn * 32 + nf * 8 + 2 * q;
                float2 fd = fd2[(long)row * 64 + (col >> 1)];
                float c0 = acc[mf][nf][half * 2 + 0];
                float c1 = acc[mf][nf][half * 2 + 1];
                float2 o;
                o.x = c0 + cdst * fd.x + bcs[col];
                o.y = c1 + cdst * fd.y + bcs[col + 1];
                out2[(long)row * 64 + (col >> 1)] = o;
            }
        }
    }
}

extern "C" void kernel_launch(void* const* d_in, const int* in_sizes, int n_in,
                              void* d_out, int out_size) {
    const float* fsrc = (const float*)d_in[0];
    const float* fdst = (const float*)d_in[1];
    const int*   isrc = (const int*)d_in[2];
    const int*   idst = (const int*)d_in[3];
    const int*   xsrc = (const int*)d_in[4];
    const int*   xdst = (const int*)d_in[5];
    const float* W    = (const float*)d_in[6];
    const float* al   = (const float*)d_in[7];
    const float* ar   = (const float*)d_in[8];
    const float* bias = (const float*)d_in[9];
    const float* lam  = (const float*)d_in[10];
    float* out = (float*)d_out;

    int n = in_sizes[0] / DD;
    int E = in_sizes[2];
    int len = 4 * n;
    int nb1 = (len + 1023) / 1024;

    static int configured = 0;
    if (!configured) {
        cudaFuncSetAttribute(k_gemm_mma, cudaFuncAttributeMaxDynamicSharedMemorySize,
                             GEMM_SMEM_BYTES);
        configured = 1;
    }

    k_prep2<<<8, 256>>>(W, al, ar, lam);
    k_elr<<<(n + 7) / 8, 256>>>(fsrc, fdst, n);
    k_zero<<<(len + 255) / 256, 256>>>(len);
    k_hist<<<(4 * E + 255) / 256, 256>>>(isrc, idst, xsrc, xdst, n, E);
    k_scan1<<<nb1, 1024>>>(len);
    k_scan2<<<1, 512>>>(nb1);
    k_scan3<<<nb1, 1024>>>(len);
    k_fill<<<(4 * E + 255) / 256, 256>>>(isrc, idst, xsrc, xdst, n, E);
    k_agg<<<dim3((n + 3) / 4, 4), 128>>>(n, E);
    k_gemm_mma<<<(n + 127) / 128, 256, GEMM_SMEM_BYTES>>>(lam, bias, fdst, out, n);
}

// round 6
// speedup vs baseline: 2.1758x; 1.0484x over previous
#include <cuda_runtime.h>
#include <cuda_bf16.h>
#include <cuda_fp16.h>
#include <math.h>
#include <stdint.h>

#define MAXN 100000
#define NPAD 100096            // padded row stride for g_Y (last GEMM tile reads in-bounds)
#define MAXE 600000
#define DD 128

// ---------------- static device scratch (no allocations allowed) ----------------
__device__ __align__(256) __half g_Y[8L * NPAD * DD];   // Y_r = S_r X_r (fp16)
__device__ __align__(256) __half g_Bt[8 * DD * DD];     // Bt[r][n][k] = fp16(lam * W[r][k][n])
__device__ __nv_bfloat16 g_fsH[MAXN * DD];              // bf16 mirror of feat_src
__device__ __nv_bfloat16 g_fdH[MAXN * DD];              // bf16 mirror of feat_dst
__device__ float g_el[8 * MAXN];
__device__ float g_er[8 * MAXN];
__device__ float g_wal[8 * DD];
__device__ float g_war[8 * DD];
__device__ int   g_cnt[4 * MAXN];
__device__ int   g_rowptr[4 * MAXN];
__device__ int   g_cursor[4 * MAXN];
__device__ int   g_col[4 * MAXE];
__device__ int   g_bsums[1024];
__device__ int   g_boffs[1024];

__device__ __forceinline__ uint32_t smem_u32(const void* p) {
    uint32_t a;
    asm("{ .reg .u64 t; cvta.to.shared.u64 t, %1; cvt.u32.u64 %0, t; }" : "=r"(a) : "l"(p));
    return a;
}
__device__ __forceinline__ void cp16(uint32_t dst, const void* src) {
    asm volatile("cp.async.ca.shared.global [%0], [%1], 16;" :: "r"(dst), "l"(src));
}
#define CP_COMMIT() asm volatile("cp.async.commit_group;" ::: "memory")
#define CP_WAIT(N)  asm volatile("cp.async.wait_group %0;" :: "n"(N) : "memory")

__device__ __forceinline__ float2 bf2f(uint32_t u) {
    __nv_bfloat162 h = *reinterpret_cast<__nv_bfloat162*>(&u);
    return __bfloat1622float2(h);
}

// ---------------- prep: wal/war dots + Bt transpose-scale (fp16) ----------------
__global__ void k_prep2(const float* __restrict__ W, const float* __restrict__ al,
                        const float* __restrict__ ar, const float* __restrict__ lam) {
    int r = blockIdx.x, t = threadIdx.x;
    if (t < 128) {
        const float* Wr  = W + r * DD * DD + t * DD;
        const float* alr = al + r * DD;
        const float* arr = ar + r * DD;
        float sl = 0.f, sr = 0.f;
        #pragma unroll 8
        for (int j = 0; j < DD; j++) { float w = Wr[j]; sl += w * alr[j]; sr += w * arr[j]; }
        g_wal[r * DD + t] = sl;
        g_war[r * DD + t] = sr;
    }
    float lr = lam[r >> 1];
    for (int i = t; i < DD * DD; i += 256) {
        int nn = i >> 7, kk = i & 127;
        g_Bt[r * DD * DD + i] = __float2half_rn(lr * W[(r * DD + kk) * DD + nn]);
    }
}

// ---------------- el/er matvecs + bf16 feature mirrors ----------------
__global__ void k_elr(const float* __restrict__ fsrc, const float* __restrict__ fdst, int n) {
    __shared__ float4 swal[8 * 32], swar[8 * 32];
    int tid = threadIdx.x;
    if (tid < 256) {
        swal[tid] = ((const float4*)g_wal)[tid];
        swar[tid] = ((const float4*)g_war)[tid];
    }
    __syncthreads();
    int warp = tid >> 5, lane = tid & 31;
    int node = blockIdx.x * 8 + warp;
    if (node >= n) return;
    float4 fs = ((const float4*)fsrc)[(long)node * 32 + lane];
    float4 fd = ((const float4*)fdst)[(long)node * 32 + lane];

    {
        __nv_bfloat162 a0 = __floats2bfloat162_rn(fs.x, fs.y);
        __nv_bfloat162 a1 = __floats2bfloat162_rn(fs.z, fs.w);
        __nv_bfloat162 b0 = __floats2bfloat162_rn(fd.x, fd.y);
        __nv_bfloat162 b1 = __floats2bfloat162_rn(fd.z, fd.w);
        uint2 ua, ub;
        ua.x = *reinterpret_cast<uint32_t*>(&a0); ua.y = *reinterpret_cast<uint32_t*>(&a1);
        ub.x = *reinterpret_cast<uint32_t*>(&b0); ub.y = *reinterpret_cast<uint32_t*>(&b1);
        ((uint2*)g_fsH)[(long)node * 32 + lane] = ua;
        ((uint2*)g_fdH)[(long)node * 32 + lane] = ub;
    }

    float p[16];
    #pragma unroll
    for (int r = 0; r < 8; r++) {
        float4 wl = swal[r * 32 + lane];
        float4 wr = swar[r * 32 + lane];
        bool useSrc = (r == 0 || r == 1 || r == 4 || r == 5);
        float4 x = useSrc ? fs : fd;
        p[r]     = x.x * wl.x + x.y * wl.y + x.z * wl.z + x.w * wl.w;
        p[8 + r] = fd.x * wr.x + fd.y * wr.y + fd.z * wr.z + fd.w * wr.w;
    }
    #pragma unroll
    for (int i = 0; i < 16; i++)
        #pragma unroll
        for (int o = 16; o; o >>= 1) p[i] += __shfl_xor_sync(0xffffffffu, p[i], o);
    if (lane == 0) {
        #pragma unroll
        for (int r = 0; r < 8; r++) {
            g_el[(long)r * n + node] = p[r];
            g_er[(long)r * n + node] = p[8 + r];
        }
    }
}

__global__ void k_zero(int len) {
    int i = blockIdx.x * blockDim.x + threadIdx.x;
    if (i < len) g_cnt[i] = 0;
}

__global__ void k_hist(const int* __restrict__ isrc, const int* __restrict__ idst,
                       const int* __restrict__ xsrc, const int* __restrict__ xdst,
                       int n, int E) {
    int t = blockIdx.x * blockDim.x + threadIdx.x;
    if (t >= 4 * E) return;
    int s = t / E, e = t - s * E;
    int key = (s == 0) ? idst[e] : (s == 1) ? xdst[e] : (s == 2) ? isrc[e] : xsrc[e];
    atomicAdd(&g_cnt[s * n + key], 1);
}

__global__ void k_scan1(int len) {
    __shared__ int sm[1024];
    int i = blockIdx.x * 1024 + threadIdx.x;
    int v = (i < len) ? g_cnt[i] : 0;
    sm[threadIdx.x] = v;
    __syncthreads();
    for (int off = 1; off < 1024; off <<= 1) {
        int t = (threadIdx.x >= off) ? sm[threadIdx.x - off] : 0;
        __syncthreads();
        sm[threadIdx.x] += t;
        __syncthreads();
    }
    if (i < len) g_rowptr[i] = sm[threadIdx.x];
    if (threadIdx.x == 1023) g_bsums[blockIdx.x] = sm[1023];
}

__global__ void k_scan2(int nb) {
    __shared__ int sm[512];
    int v = (threadIdx.x < nb) ? g_bsums[threadIdx.x] : 0;
    sm[threadIdx.x] = v;
    __syncthreads();
    for (int off = 1; off < 512; off <<= 1) {
        int t = (threadIdx.x >= off) ? sm[threadIdx.x - off] : 0;
        __syncthreads();
        sm[threadIdx.x] += t;
        __syncthreads();
    }
    if (threadIdx.x < nb) g_boffs[threadIdx.x] = sm[threadIdx.x] - v;
}

__global__ void k_scan3(int len) {
    int i = blockIdx.x * 1024 + threadIdx.x;
    if (i >= len) return;
    int excl = g_rowptr[i] - g_cnt[i] + g_boffs[blockIdx.x];
    g_rowptr[i] = excl;
    g_cursor[i] = excl;
}

__global__ void k_fill(const int* __restrict__ isrc, const int* __restrict__ idst,
                       const int* __restrict__ xsrc, const int* __restrict__ xdst,
                       int n, int E) {
    int t = blockIdx.x * blockDim.x + threadIdx.x;
    if (t >= 4 * E) return;
    int s = t / E, e = t - s * E;
    int key, col;
    if (s == 0)      { key = idst[e]; col = isrc[e]; }
    else if (s == 1) { key = xdst[e]; col = xsrc[e]; }
    else if (s == 2) { key = isrc[e]; col = idst[e]; }
    else             { key = xsrc[e]; col = xdst[e]; }
    int pos = atomicAdd(&g_cursor[s * n + key], 1);
    g_col[pos] = col;
}

__device__ __forceinline__ float lrelu(float x) { return x > 0.f ? x : 0.2f * x; }

// ---------------- edge-softmax (no max pass) + bf16 gather aggregation ----------------
__global__ void k_agg(int n, int E) {
    int s = blockIdx.y;
    int warp = threadIdx.x >> 5, lane = threadIdx.x & 31;
    int node = blockIdx.x * 4 + warp;
    if (node >= n) return;
    int ra = (s < 2) ? s : s + 2;
    int rb = ra + 2;
    long idx = (long)s * n + node;
    int start = g_rowptr[idx];
    int end   = (idx + 1 < 4L * n) ? g_rowptr[idx + 1] : 4 * E;

    const float* ela = g_el + (long)ra * n;
    const float* elb = g_el + (long)rb * n;
    float era = g_er[(long)ra * n + node];
    float erb = g_er[(long)rb * n + node];

    float4 acca = make_float4(0, 0, 0, 0), accb = make_float4(0, 0, 0, 0);
    float dena = 0.f, denb = 0.f;
    const uint2* fs2 = (const uint2*)g_fsH;
    const uint2* fd2 = (const uint2*)g_fdH;

    for (int base = start; base < end; base += 32) {
        int k = base + lane;
        int c = 0; float wa = 0.f, wb = 0.f;
        if (k < end) {
            c = __ldg(&g_col[k]);
            wa = __expf(lrelu(ela[c] + era));
            wb = __expf(lrelu(elb[c] + erb));
        }
        dena += wa; denb += wb;
        int num = min(32, end - base);
        int j = 0;
        for (; j + 3 < num; j += 4) {
            int cj[4]; float waj[4], wbj[4];
            #pragma unroll
            for (int u = 0; u < 4; u++) {
                cj[u]  = __shfl_sync(0xffffffffu, c,  j + u);
                waj[u] = __shfl_sync(0xffffffffu, wa, j + u);
                wbj[u] = __shfl_sync(0xffffffffu, wb, j + u);
            }
            uint2 ua[4], ub[4];
            #pragma unroll
            for (int u = 0; u < 4; u++) {
                ua[u] = fs2[(long)cj[u] * 32 + lane];
                ub[u] = fd2[(long)cj[u] * 32 + lane];
            }
            #pragma unroll
            for (int u = 0; u < 4; u++) {
                float2 a0 = bf2f(ua[u].x), a1 = bf2f(ua[u].y);
                float2 b0 = bf2f(ub[u].x), b1 = bf2f(ub[u].y);
                acca.x += waj[u] * a0.x; acca.y += waj[u] * a0.y;
                acca.z += waj[u] * a1.x; acca.w += waj[u] * a1.y;
                accb.x += wbj[u] * b0.x; accb.y += wbj[u] * b0.y;
                accb.z += wbj[u] * b1.x; accb.w += wbj[u] * b1.y;
            }
        }
        for (; j < num; j++) {
            int   c0  = __shfl_sync(0xffffffffu, c,  j);
            float wa0 = __shfl_sync(0xffffffffu, wa, j);
            float wb0 = __shfl_sync(0xffffffffu, wb, j);
            uint2 ua0 = fs2[(long)c0 * 32 + lane];
            uint2 ub0 = fd2[(long)c0 * 32 + lane];
            float2 a00 = bf2f(ua0.x), a01 = bf2f(ua0.y);
            float2 b00 = bf2f(ub0.x), b01 = bf2f(ub0.y);
            acca.x += wa0 * a00.x; acca.y += wa0 * a00.y;
            acca.z += wa0 * a01.x; acca.w += wa0 * a01.y;
            accb.x += wb0 * b00.x; accb.y += wb0 * b00.y;
            accb.z += wb0 * b01.x; accb.w += wb0 * b01.y;
        }
    }
    #pragma unroll
    for (int o = 16; o; o >>= 1) {
        dena += __shfl_xor_sync(0xffffffffu, dena, o);
        denb += __shfl_xor_sync(0xffffffffu, denb, o);
    }
    float inva = 1.0f / fmaxf(dena, 1e-9f);
    float invb = 1.0f / fmaxf(denb, 1e-9f);
    __half2 ha0 = __floats2half2_rn(acca.x * inva, acca.y * inva);
    __half2 ha1 = __floats2half2_rn(acca.z * inva, acca.w * inva);
    __half2 hb0 = __floats2half2_rn(accb.x * invb, accb.y * invb);
    __half2 hb1 = __floats2half2_rn(accb.z * invb, accb.w * invb);
    uint2 ya, yb;
    ya.x = *reinterpret_cast<uint32_t*>(&ha0); ya.y = *reinterpret_cast<uint32_t*>(&ha1);
    yb.x = *reinterpret_cast<uint32_t*>(&hb0); yb.y = *reinterpret_cast<uint32_t*>(&hb1);
    __stcs(((uint2*)g_Y) + ((long)ra * NPAD + node) * 32 + lane, ya);
    __stcs(((uint2*)g_Y) + ((long)rb * NPAD + node) * 32 + lane, yb);
}

// =================== mma.sync fp16 fused GEMM, cp.async double-buffered ===================
// Byte layout in dynamic smem:
//   As[2][128][144B]  at 0      (36864 B)
//   Bs[2][128][144B]  at 36864  (36864 B)
//   bcs[128] float    at 73728  (512 B)
#define AS_OFF 0
#define BS_OFF 36864
#define BC_OFF 73728
#define GEMM_SMEM_BYTES (73728 + 512)
#define BUFB 18432            // one buffer = 128 rows * 144 B

__device__ __forceinline__ void mma_f16(float* c, const uint32_t* a, const uint32_t* b) {
    asm volatile(
        "mma.sync.aligned.m16n8k16.row.col.f32.f16.f16.f32 "
        "{%0,%1,%2,%3}, {%4,%5,%6,%7}, {%8,%9}, {%0,%1,%2,%3};"
        : "+f"(c[0]), "+f"(c[1]), "+f"(c[2]), "+f"(c[3])
        : "r"(a[0]), "r"(a[1]), "r"(a[2]), "r"(a[3]), "r"(b[0]), "r"(b[1]));
}

__global__ void __launch_bounds__(256, 2) k_gemm_mma(
    const float* __restrict__ lam, const float* __restrict__ bias,
    const float* __restrict__ fdst, float* __restrict__ out, int n) {
    extern __shared__ char smc[];
    float* bcs = (float*)(smc + BC_OFF);
    uint32_t sm_base = smem_u32(smc);

    int tid = threadIdx.x, wid = tid >> 5, lane = tid & 31;
    int wm = wid & 1, wn = wid >> 1;
    int row0 = blockIdx.x * 128;
    int g = lane >> 2, q = lane & 3;

    if (tid < 128) {
        float s = 0.f;
        #pragma unroll
        for (int t = 0; t < 4; t++)
            s += lam[t] * (bias[(2 * t) * DD + tid] + bias[(2 * t + 1) * DD + tid]);
        bcs[tid] = s;
    }

    float acc[4][4][4];
    #pragma unroll
    for (int i = 0; i < 4; i++)
        #pragma unroll
        for (int j = 0; j < 4; j++)
            #pragma unroll
            for (int t = 0; t < 4; t++) acc[i][j][t] = 0.f;

    int lrow = tid >> 1;               // 0..127
    int lseg = (tid & 1) * 64;         // byte half of 128B row-chunk

    // chunk c: relation r = c>>1, K-half (c&1) -> 64 halves = 128 bytes
    auto issue = [&](int c, int buf) {
        int r = c >> 1;
        int koff = (c & 1) * 128;
        const char* ys = (const char*)g_Y + ((long)r * NPAD + row0 + lrow) * 256 + koff + lseg;
        const char* bs = (const char*)g_Bt + ((long)r * DD + lrow) * 256 + koff + lseg;
        uint32_t ad = sm_base + AS_OFF + (uint32_t)buf * BUFB + (uint32_t)lrow * 144 + lseg;
        uint32_t bd = sm_base + BS_OFF + (uint32_t)buf * BUFB + (uint32_t)lrow * 144 + lseg;
        #pragma unroll
        for (int i = 0; i < 4; i++) {
            cp16(ad + i * 16, ys + i * 16);
            cp16(bd + i * 16, bs + i * 16);
        }
        CP_COMMIT();
    };

    issue(0, 0);
    #pragma unroll 1
    for (int c = 0; c < 16; c++) {
        int buf = c & 1;
        if (c < 15) { issue(c + 1, buf ^ 1); CP_WAIT(1); }
        else        { CP_WAIT(0); }
        __syncthreads();
        const char* Ab = smc + AS_OFF + buf * BUFB;
        const char* Bb = smc + BS_OFF + buf * BUFB;
        #pragma unroll
        for (int ks = 0; ks < 4; ks++) {
            int kb = ks * 16;                       // halves
            int kbyte = (kb + 2 * q) * 2;
            uint32_t a[4][4], b[4][2];
            #pragma unroll
            for (int mf = 0; mf < 4; mf++) {
                int m = wm * 64 + mf * 16;
                const char* p0 = Ab + (m + g) * 144 + kbyte;
                const char* p1 = Ab + (m + g + 8) * 144 + kbyte;
                a[mf][0] = *(const uint32_t*)p0;
                a[mf][1] = *(const uint32_t*)p1;
                a[mf][2] = *(const uint32_t*)(p0 + 16);
                a[mf][3] = *(const uint32_t*)(p1 + 16);
            }
            #pragma unroll
            for (int nf = 0; nf < 4; nf++) {
                int nn = wn * 32 + nf * 8 + g;
                const char* p = Bb + nn * 144 + kbyte;
                b[nf][0] = *(const uint32_t*)p;
                b[nf][1] = *(const uint32_t*)(p + 16);
            }
            #pragma unroll
            for (int mf = 0; mf < 4; mf++)
                #pragma unroll
                for (int nf = 0; nf < 4; nf++)
                    mma_f16(acc[mf][nf], a[mf], b[nf]);
        }
        __syncthreads();
    }

    float cdst = 2.0f * (__ldg(&lam[0]) + __ldg(&lam[1]) + __ldg(&lam[2]) + __ldg(&lam[3]));
    float2* out2 = (float2*)out;
    const float2* fd2 = (const float2*)fdst;
    #pragma unroll
    for (int mf = 0; mf < 4; mf++) {
        #pragma unroll
        for (int half = 0; half < 2; half++) {
            int row = row0 + wm * 64 + mf * 16 + g + half * 8;
            if (row >= n) continue;
            #pragma unroll
            for (int nf = 0; nf < 4; nf++) {
                int col = wn * 32 + nf * 8 + 2 * q;
                float2 fd = fd2[(long)row * 64 + (col >> 1)];
                float c0 = acc[mf][nf][half * 2 + 0];
                float c1 = acc[mf][nf][half * 2 + 1];
                float2 o;
                o.x = c0 + cdst * fd.x + bcs[col];
                o.y = c1 + cdst * fd.y + bcs[col + 1];
                out2[(long)row * 64 + (col >> 1)] = o;
            }
        }
    }
}

extern "C" void kernel_launch(void* const* d_in, const int* in_sizes, int n_in,
                              void* d_out, int out_size) {
    const float* fsrc = (const float*)d_in[0];
    const float* fdst = (const float*)d_in[1];
    const int*   isrc = (const int*)d_in[2];
    const int*   idst = (const int*)d_in[3];
    const int*   xsrc = (const int*)d_in[4];
    const int*   xdst = (const int*)d_in[5];
    const float* W    = (const float*)d_in[6];
    const float* al   = (const float*)d_in[7];
    const float* ar   = (const float*)d_in[8];
    const float* bias = (const float*)d_in[9];
    const float* lam  = (const float*)d_in[10];
    float* out = (float*)d_out;

    int n = in_sizes[0] / DD;
    int E = in_sizes[2];
    int len = 4 * n;
    int nb1 = (len + 1023) / 1024;

    static int configured = 0;
    static cudaStream_t s1;
    static cudaEvent_t evFork, evJoin;
    if (!configured) {
        cudaFuncSetAttribute(k_gemm_mma, cudaFuncAttributeMaxDynamicSharedMemorySize,
                             GEMM_SMEM_BYTES);
        cudaStreamCreateWithFlags(&s1, cudaStreamNonBlocking);
        cudaEventCreateWithFlags(&evFork, cudaEventDisableTiming);
        cudaEventCreateWithFlags(&evJoin, cudaEventDisableTiming);
        configured = 1;
    }

    // fork: CSR-build chain on s1, el/er chain on the launch stream
    cudaEventRecord(evFork, 0);
    cudaStreamWaitEvent(s1, evFork, 0);

    k_zero<<<(len + 255) / 256, 256, 0, s1>>>(len);
    k_hist<<<(4 * E + 255) / 256, 256, 0, s1>>>(isrc, idst, xsrc, xdst, n, E);
    k_scan1<<<nb1, 1024, 0, s1>>>(len);
    k_scan2<<<1, 512, 0, s1>>>(nb1);
    k_scan3<<<nb1, 1024, 0, s1>>>(len);
    k_fill<<<(4 * E + 255) / 256, 256, 0, s1>>>(isrc, idst, xsrc, xdst, n, E);
    cudaEventRecord(evJoin, s1);

    k_prep2<<<8, 256>>>(W, al, ar, lam);
    k_elr<<<(n + 7) / 8, 256>>>(fsrc, fdst, n);

    cudaStreamWaitEvent(0, evJoin, 0);   // join before agg
    k_agg<<<dim3((n + 3) / 4, 4), 128>>>(n, E);
    k_gemm_mma<<<(n + 127) / 128, 256, GEMM_SMEM_BYTES>>>(lam, bias, fdst, out, n);
}

// round 7
// speedup vs baseline: 2.2153x; 1.0182x over previous
#include <cuda_runtime.h>
#include <cuda_bf16.h>
#include <cuda_fp16.h>
#include <math.h>
#include <stdint.h>

#define MAXN 100000
#define NPAD 100096
#define MAXE 600000
#define DD 128

// ---------------- static device scratch (zero-initialized at load) ----------------
__device__ __align__(256) __half g_Y[8L * NPAD * DD];   // Y_r = S_r X_r (fp16)
__device__ __align__(256) __half g_Bt[8 * DD * DD];     // fp16(lam * W^T)
__device__ __nv_bfloat16 g_fI[MAXN * 2 * DD];           // per node: 128 bf16 fsrc | 128 bf16 fdst
__device__ float g_el[8 * MAXN];
__device__ float g_er[8 * MAXN];
__device__ float g_wal[8 * DD];
__device__ float g_war[8 * DD];
__device__ int   g_cnt[4 * MAXN];     // zeroed at load; re-zeroed by scanLB each run
__device__ int   g_rowptr[4 * MAXN];
__device__ int   g_cursor[4 * MAXN];
__device__ int   g_col[4 * MAXE];
// decoupled-lookback state (reset by last block each run)
__device__ volatile int g_stat[512];
__device__ int g_aggv[512];
__device__ int g_prefv[512];
__device__ int g_done;

__device__ __forceinline__ uint32_t smem_u32(const void* p) {
    uint32_t a;
    asm("{ .reg .u64 t; cvta.to.shared.u64 t, %1; cvt.u32.u64 %0, t; }" : "=r"(a) : "l"(p));
    return a;
}
__device__ __forceinline__ void cp16(uint32_t dst, const void* src) {
    asm volatile("cp.async.ca.shared.global [%0], [%1], 16;" :: "r"(dst), "l"(src));
}
#define CP_COMMIT() asm volatile("cp.async.commit_group;" ::: "memory")
#define CP_WAIT(N)  asm volatile("cp.async.wait_group %0;" :: "n"(N) : "memory")

__device__ __forceinline__ float2 bf2f(uint32_t u) {
    __nv_bfloat162 h = *reinterpret_cast<__nv_bfloat162*>(&u);
    return __bfloat1622float2(h);
}
__device__ __forceinline__ float lrelu(float x) { return x > 0.f ? x : 0.2f * x; }

// ============ 1) hist + (blocks 0-7) wal/war/Bt prep ============
__global__ void k_hist_prep(const int* __restrict__ isrc, const int* __restrict__ idst,
                            const int* __restrict__ xsrc, const int* __restrict__ xdst,
                            const float* __restrict__ W, const float* __restrict__ al,
                            const float* __restrict__ ar, const float* __restrict__ lam,
                            int n, int E) {
    int bid = blockIdx.x, tid = threadIdx.x;
    if (bid < 8) {
        int r = bid;
        if (tid < 128) {
            const float* Wr  = W + r * DD * DD + tid * DD;
            const float* alr = al + r * DD;
            const float* arr = ar + r * DD;
            float sl = 0.f, sr = 0.f;
            #pragma unroll 8
            for (int j = 0; j < DD; j++) { float w = Wr[j]; sl += w * alr[j]; sr += w * arr[j]; }
            g_wal[r * DD + tid] = sl;
            g_war[r * DD + tid] = sr;
        }
        float lr = lam[r >> 1];
        for (int i = tid; i < DD * DD; i += 256) {
            int nn = i >> 7, kk = i & 127;
            g_Bt[r * DD * DD + i] = __float2half_rn(lr * W[(r * DD + kk) * DD + nn]);
        }
    }
    int t = bid * 256 + tid;
    if (t >= 4 * E) return;
    int s = t / E, e = t - s * E;
    int key = (s == 0) ? idst[e] : (s == 1) ? xdst[e] : (s == 2) ? isrc[e] : xsrc[e];
    atomicAdd(&g_cnt[s * n + key], 1);
}

// ============ 2) single-pass decoupled-lookback scan ============
// rowptr/cursor = exclusive prefix of g_cnt; re-zeros g_cnt; resets lookback state.
__global__ void k_scanLB(int len) {
    __shared__ int sm[1024];
    __shared__ int s_pref;
    int b = blockIdx.x, tid = threadIdx.x;
    int i = b * 1024 + tid;
    int v = (i < len) ? g_cnt[i] : 0;
    sm[tid] = v;
    __syncthreads();
    for (int off = 1; off < 1024; off <<= 1) {
        int t = (tid >= off) ? sm[tid - off] : 0;
        __syncthreads();
        sm[tid] += t;
        __syncthreads();
    }
    int incl = sm[tid];
    if (tid == 1023) {
        int total = incl;
        if (b == 0) {
            g_prefv[0] = total;
            __threadfence();
            g_stat[0] = 2;
            s_pref = 0;
        } else {
            g_aggv[b] = total;
            __threadfence();
            g_stat[b] = 1;
            int pref = 0;
            for (int j = b - 1; j >= 0;) {
                int st;
                do { st = g_stat[j]; } while (st == 0);
                __threadfence();
                if (st == 2) { pref += g_prefv[j]; break; }
                pref += g_aggv[j]; j--;
            }
            g_prefv[b] = pref + total;
            __threadfence();
            g_stat[b] = 2;
            s_pref = pref;
        }
    }
    __syncthreads();
    int pref = s_pref;
    if (i < len) {
        int excl = incl - v + pref;
        g_rowptr[i] = excl;
        g_cursor[i] = excl;
        g_cnt[i] = 0;                  // ready for next replay
    }
    __syncthreads();
    if (tid == 0) {
        int d = atomicAdd(&g_done, 1);
        if (d == gridDim.x - 1) {      // last block: reset lookback state
            for (int j = 0; j < gridDim.x; j++) g_stat[j] = 0;
            g_done = 0;
            __threadfence();
        }
    }
}

// ============ 3) fill (blocks [0,fillB)) + elr/mirror (blocks [fillB, ...)) ============
__global__ void k_fill_elr(const int* __restrict__ isrc, const int* __restrict__ idst,
                           const int* __restrict__ xsrc, const int* __restrict__ xdst,
                           const float* __restrict__ fsrc, const float* __restrict__ fdst,
                           int n, int E, int fillB) {
    __shared__ float4 swal[8 * 32], swar[8 * 32];
    int bid = blockIdx.x, tid = threadIdx.x;
    if (bid < fillB) {
        int t = bid * 256 + tid;
        if (t >= 4 * E) return;
        int s = t / E, e = t - s * E;
        int key, col;
        if (s == 0)      { key = idst[e]; col = isrc[e]; }
        else if (s == 1) { key = xdst[e]; col = xsrc[e]; }
        else if (s == 2) { key = isrc[e]; col = idst[e]; }
        else             { key = xsrc[e]; col = xdst[e]; }
        int pos = atomicAdd(&g_cursor[s * n + key], 1);
        g_col[pos] = col;
        return;
    }
    // elr part
    if (tid < 256) {
        swal[tid] = ((const float4*)g_wal)[tid];
        swar[tid] = ((const float4*)g_war)[tid];
    }
    __syncthreads();
    int warp = tid >> 5, lane = tid & 31;
    int node = (bid - fillB) * 8 + warp;
    if (node >= n) return;
    float4 fs = ((const float4*)fsrc)[(long)node * 32 + lane];
    float4 fd = ((const float4*)fdst)[(long)node * 32 + lane];
    {
        __nv_bfloat162 a0 = __floats2bfloat162_rn(fs.x, fs.y);
        __nv_bfloat162 a1 = __floats2bfloat162_rn(fs.z, fs.w);
        __nv_bfloat162 b0 = __floats2bfloat162_rn(fd.x, fd.y);
        __nv_bfloat162 b1 = __floats2bfloat162_rn(fd.z, fd.w);
        uint2 ua, ub;
        ua.x = *reinterpret_cast<uint32_t*>(&a0); ua.y = *reinterpret_cast<uint32_t*>(&a1);
        ub.x = *reinterpret_cast<uint32_t*>(&b0); ub.y = *reinterpret_cast<uint32_t*>(&b1);
        ((uint2*)g_fI)[((long)node << 6) + lane] = ua;
        ((uint2*)g_fI)[((long)node << 6) + 32 + lane] = ub;
    }
    float p[16];
    #pragma unroll
    for (int r = 0; r < 8; r++) {
        float4 wl = swal[r * 32 + lane];
        float4 wr = swar[r * 32 + lane];
        bool useSrc = (r == 0 || r == 1 || r == 4 || r == 5);
        float4 x = useSrc ? fs : fd;
        p[r]     = x.x * wl.x + x.y * wl.y + x.z * wl.z + x.w * wl.w;
        p[8 + r] = fd.x * wr.x + fd.y * wr.y + fd.z * wr.z + fd.w * wr.w;
    }
    #pragma unroll
    for (int i = 0; i < 16; i++)
        #pragma unroll
        for (int o = 16; o; o >>= 1) p[i] += __shfl_xor_sync(0xffffffffu, p[i], o);
    if (lane == 0) {
        #pragma unroll
        for (int r = 0; r < 8; r++) {
            g_el[(long)r * n + node] = p[r];
            g_er[(long)r * n + node] = p[8 + r];
        }
    }
}

// ============ 4) edge-softmax (no max pass) + interleaved bf16 gather agg ============
__global__ void k_agg(int n, int E) {
    int s = blockIdx.y;
    int warp = threadIdx.x >> 5, lane = threadIdx.x & 31;
    int node = blockIdx.x * 4 + warp;
    if (node >= n) return;
    int ra = (s < 2) ? s : s + 2;
    int rb = ra + 2;
    long idx = (long)s * n + node;
    int start = g_rowptr[idx];
    int end   = (idx + 1 < 4L * n) ? g_rowptr[idx + 1] : 4 * E;

    const float* ela = g_el + (long)ra * n;
    const float* elb = g_el + (long)rb * n;
    float era = g_er[(long)ra * n + node];
    float erb = g_er[(long)rb * n + node];

    float4 acca = make_float4(0, 0, 0, 0), accb = make_float4(0, 0, 0, 0);
    float dena = 0.f, denb = 0.f;
    const uint2* fI2 = (const uint2*)g_fI;

    for (int base = start; base < end; base += 32) {
        int k = base + lane;
        int c = 0; float wa = 0.f, wb = 0.f;
        if (k < end) {
            c = __ldg(&g_col[k]);
            wa = __expf(lrelu(ela[c] + era));
            wb = __expf(lrelu(elb[c] + erb));
        }
        dena += wa; denb += wb;
        int num = min(32, end - base);
        int j = 0;
        for (; j + 3 < num; j += 4) {
            int cj[4]; float waj[4], wbj[4];
            #pragma unroll
            for (int u = 0; u < 4; u++) {
                cj[u]  = __shfl_sync(0xffffffffu, c,  j + u);
                waj[u] = __shfl_sync(0xffffffffu, wa, j + u);
                wbj[u] = __shfl_sync(0xffffffffu, wb, j + u);
            }
            uint2 ua[4], ub[4];
            #pragma unroll
            for (int u = 0; u < 4; u++) {
                long b0 = (long)cj[u] << 6;
                ua[u] = fI2[b0 + lane];
                ub[u] = fI2[b0 + 32 + lane];
            }
            #pragma unroll
            for (int u = 0; u < 4; u++) {
                float2 a0 = bf2f(ua[u].x), a1 = bf2f(ua[u].y);
                float2 b0 = bf2f(ub[u].x), b1 = bf2f(ub[u].y);
                acca.x += waj[u] * a0.x; acca.y += waj[u] * a0.y;
                acca.z += waj[u] * a1.x; acca.w += waj[u] * a1.y;
                accb.x += wbj[u] * b0.x; accb.y += wbj[u] * b0.y;
                accb.z += wbj[u] * b1.x; accb.w += wbj[u] * b1.y;
            }
        }
        for (; j < num; j++) {
            int   c0  = __shfl_sync(0xffffffffu, c,  j);
            float wa0 = __shfl_sync(0xffffffffu, wa, j);
            float wb0 = __shfl_sync(0xffffffffu, wb, j);
            long b0i = (long)c0 << 6;
            uint2 ua0 = fI2[b0i + lane];
            uint2 ub0 = fI2[b0i + 32 + lane];
            float2 a00 = bf2f(ua0.x), a01 = bf2f(ua0.y);
            float2 b00 = bf2f(ub0.x), b01 = bf2f(ub0.y);
            acca.x += wa0 * a00.x; acca.y += wa0 * a00.y;
            acca.z += wa0 * a01.x; acca.w += wa0 * a01.y;
            accb.x += wb0 * b00.x; accb.y += wb0 * b00.y;
            accb.z += wb0 * b01.x; accb.w += wb0 * b01.y;
        }
    }
    #pragma unroll
    for (int o = 16; o; o >>= 1) {
        dena += __shfl_xor_sync(0xffffffffu, dena, o);
        denb += __shfl_xor_sync(0xffffffffu, denb, o);
    }
    float inva = 1.0f / fmaxf(dena, 1e-9f);
    float invb = 1.0f / fmaxf(denb, 1e-9f);
    __half2 ha0 = __floats2half2_rn(acca.x * inva, acca.y * inva);
    __half2 ha1 = __floats2half2_rn(acca.z * inva, acca.w * inva);
    __half2 hb0 = __floats2half2_rn(accb.x * invb, accb.y * invb);
    __half2 hb1 = __floats2half2_rn(accb.z * invb, accb.w * invb);
    uint2 ya, yb;
    ya.x = *reinterpret_cast<uint32_t*>(&ha0); ya.y = *reinterpret_cast<uint32_t*>(&ha1);
    yb.x = *reinterpret_cast<uint32_t*>(&hb0); yb.y = *reinterpret_cast<uint32_t*>(&hb1);
    __stcs(((uint2*)g_Y) + ((long)ra * NPAD + node) * 32 + lane, ya);
    __stcs(((uint2*)g_Y) + ((long)rb * NPAD + node) * 32 + lane, yb);
}

// ============ 5) mma.sync fp16 fused GEMM, cp.async double-buffered ============
#define AS_OFF 0
#define BS_OFF 36864
#define BC_OFF 73728
#define GEMM_SMEM_BYTES (73728 + 512)
#define BUFB 18432

__device__ __forceinline__ void mma_f16(float* c, const uint32_t* a, const uint32_t* b) {
    asm volatile(
        "mma.sync.aligned.m16n8k16.row.col.f32.f16.f16.f32 "
        "{%0,%1,%2,%3}, {%4,%5,%6,%7}, {%8,%9}, {%0,%1,%2,%3};"
        : "+f"(c[0]), "+f"(c[1]), "+f"(c[2]), "+f"(c[3])
        : "r"(a[0]), "r"(a[1]), "r"(a[2]), "r"(a[3]), "r"(b[0]), "r"(b[1]));
}

__global__ void __launch_bounds__(256, 2) k_gemm_mma(
    const float* __restrict__ lam, const float* __restrict__ bias,
    const float* __restrict__ fdst, float* __restrict__ out, int n) {
    extern __shared__ char smc[];
    float* bcs = (float*)(smc + BC_OFF);
    uint32_t sm_base = smem_u32(smc);

    int tid = threadIdx.x, wid = tid >> 5, lane = tid & 31;
    int wm = wid & 1, wn = wid >> 1;
    int row0 = blockIdx.x * 128;
    int g = lane >> 2, q = lane & 3;

    if (tid < 128) {
        float s = 0.f;
        #pragma unroll
        for (int t = 0; t < 4; t++)
            s += lam[t] * (bias[(2 * t) * DD + tid] + bias[(2 * t + 1) * DD + tid]);
        bcs[tid] = s;
    }

    float acc[4][4][4];
    #pragma unroll
    for (int i = 0; i < 4; i++)
        #pragma unroll
        for (int j = 0; j < 4; j++)
            #pragma unroll
            for (int t = 0; t < 4; t++) acc[i][j][t] = 0.f;

    int lrow = tid >> 1;
    int lseg = (tid & 1) * 64;

    auto issue = [&](int c, int buf) {
        int r = c >> 1;
        int koff = (c & 1) * 128;
        const char* ys = (const char*)g_Y + ((long)r * NPAD + row0 + lrow) * 256 + koff + lseg;
        const char* bs = (const char*)g_Bt + ((long)r * DD + lrow) * 256 + koff + lseg;
        uint32_t ad = sm_base + AS_OFF + (uint32_t)buf * BUFB + (uint32_t)lrow * 144 + lseg;
        uint32_t bd = sm_base + BS_OFF + (uint32_t)buf * BUFB + (uint32_t)lrow * 144 + lseg;
        #pragma unroll
        for (int i = 0; i < 4; i++) {
            cp16(ad + i * 16, ys + i * 16);
            cp16(bd + i * 16, bs + i * 16);
        }
        CP_COMMIT();
    };

    issue(0, 0);
    #pragma unroll 1
    for (int c = 0; c < 16; c++) {
        int buf = c & 1;
        if (c < 15) { issue(c + 1, buf ^ 1); CP_WAIT(1); }
        else        { CP_WAIT(0); }
        __syncthreads();
        const char* Ab = smc + AS_OFF + buf * BUFB;
        const char* Bb = smc + BS_OFF + buf * BUFB;
        #pragma unroll
        for (int ks = 0; ks < 4; ks++) {
            int kbyte = (ks * 16 + 2 * q) * 2;
            uint32_t a[4][4], b[4][2];
            #pragma unroll
            for (int mf = 0; mf < 4; mf++) {
                int m = wm * 64 + mf * 16;
                const char* p0 = Ab + (m + g) * 144 + kbyte;
                const char* p1 = Ab + (m + g + 8) * 144 + kbyte;
                a[mf][0] = *(const uint32_t*)p0;
                a[mf][1] = *(const uint32_t*)p1;
                a[mf][2] = *(const uint32_t*)(p0 + 16);
                a[mf][3] = *(const uint32_t*)(p1 + 16);
            }
            #pragma unroll
            for (int nf = 0; nf < 4; nf++) {
                int nn = wn * 32 + nf * 8 + g;
                const char* p = Bb + nn * 144 + kbyte;
                b[nf][0] = *(const uint32_t*)p;
                b[nf][1] = *(const uint32_t*)(p + 16);
            }
            #pragma unroll
            for (int mf = 0; mf < 4; mf++)
                #pragma unroll
                for (int nf = 0; nf < 4; nf++)
                    mma_f16(acc[mf][nf], a[mf], b[nf]);
        }
        __syncthreads();
    }

    float cdst = 2.0f * (__ldg(&lam[0]) + __ldg(&lam[1]) + __ldg(&lam[2]) + __ldg(&lam[3]));
    float2* out2 = (float2*)out;
    const float2* fd2 = (const float2*)fdst;
    #pragma unroll
    for (int mf = 0; mf < 4; mf++) {
        #pragma unroll
        for (int half = 0; half < 2; half++) {
            int row = row0 + wm * 64 + mf * 16 + g + half * 8;
            if (row >= n) continue;
            #pragma unroll
            for (int nf = 0; nf < 4; nf++) {
                int col = wn * 32 + nf * 8 + 2 * q;
                float2 fd = fd2[(long)row * 64 + (col >> 1)];
                float c0 = acc[mf][nf][half * 2 + 0];
                float c1 = acc[mf][nf][half * 2 + 1];
                float2 o;
                o.x = c0 + cdst * fd.x + bcs[col];
                o.y = c1 + cdst * fd.y + bcs[col + 1];
                out2[(long)row * 64 + (col >> 1)] = o;
            }
        }
    }
}

extern "C" void kernel_launch(void* const* d_in, const int* in_sizes, int n_in,
                              void* d_out, int out_size) {
    const float* fsrc = (const float*)d_in[0];
    const float* fdst = (const float*)d_in[1];
    const int*   isrc = (const int*)d_in[2];
    const int*   idst = (const int*)d_in[3];
    const int*   xsrc = (const int*)d_in[4];
    const int*   xdst = (const int*)d_in[5];
    const float* W    = (const float*)d_in[6];
    const float* al   = (const float*)d_in[7];
    const float* ar   = (const float*)d_in[8];
    const float* bias = (const float*)d_in[9];
    const float* lam  = (const float*)d_in[10];
    float* out = (float*)d_out;

    int n = in_sizes[0] / DD;
    int E = in_sizes[2];
    int len = 4 * n;
    int nbScan = (len + 1023) / 1024;
    int fillB = (4 * E + 255) / 256;
    int elrB  = (n + 7) / 8;

    static int configured = 0;
    if (!configured) {
        cudaFuncSetAttribute(k_gemm_mma, cudaFuncAttributeMaxDynamicSharedMemorySize,
                             GEMM_SMEM_BYTES);
        configured = 1;
    }

    k_hist_prep<<<fillB, 256>>>(isrc, idst, xsrc, xdst, W, al, ar, lam, n, E);
    k_scanLB<<<nbScan, 1024>>>(len);
    k_fill_elr<<<fillB + elrB, 256>>>(isrc, idst, xsrc, xdst, fsrc, fdst, n, E, fillB);
    k_agg<<<dim3((n + 3) / 4, 4), 128>>>(n, E);
    k_gemm_mma<<<(n + 127) / 128, 256, GEMM_SMEM_BYTES>>>(lam, bias, fdst, out, n);
}